// round 3
// baseline (speedup 1.0000x reference)
#include <cuda_runtime.h>
#include <math.h>

#define BATCH 4
#define NTOK  4096
#define DIM   1024
#define NHEAD 16
#define DH    64
#define WS    128
#define NWIN  32
#define QKVN  3072

// Scratch (static device globals: allocation-free, graph-capturable)
__device__ float g_qkv[(size_t)BATCH * NTOK * QKVN];   // [16384][3072] : q | k | v
__device__ float g_attn[(size_t)BATCH * NTOK * DIM];   // [16384][1024] attention output

// ---------------------------------------------------------------------------
// 128x128x8 register-tiled SGEMM, 256 threads, 8x8 micro-tile (interleaved)
// C[M,N] = A[M,K] @ B[K,N], all row-major, M%128==0, N%128==0, K%8==0
// ---------------------------------------------------------------------------
__global__ __launch_bounds__(256) void sgemm128(const float* __restrict__ A,
                                                const float* __restrict__ Bm,
                                                float* __restrict__ C,
                                                int M, int N, int K)
{
    __shared__ float As[8 * 128];   // transposed: As[k][m]
    __shared__ float Bs[8 * 128];   // Bs[k][n]

    int tid = threadIdx.x;
    int tx = tid & 15;          // 0..15  (N direction, interleaved stride 16)
    int ty = tid >> 4;          // 0..15  (M direction, interleaved stride 16)
    int row0 = blockIdx.y * 128;
    int col0 = blockIdx.x * 128;

    int arow = tid >> 1;              // 0..127
    int acol = (tid & 1) << 2;        // 0 or 4
    int brow = tid >> 5;              // 0..7
    int bcol = (tid & 31) << 2;       // 0..124 step 4

    const float* Ap = A  + (size_t)(row0 + arow) * K + acol;
    const float* Bp = Bm + (size_t)brow * N + col0 + bcol;

    float acc[8][8];
#pragma unroll
    for (int i = 0; i < 8; i++)
#pragma unroll
        for (int j = 0; j < 8; j++) acc[i][j] = 0.f;

    for (int kt = 0; kt < K; kt += 8) {
        float4 a4 = *(const float4*)(Ap + kt);
        float4 b4 = *(const float4*)(Bp + (size_t)kt * N);
        __syncthreads();
        As[(acol + 0) * 128 + arow] = a4.x;
        As[(acol + 1) * 128 + arow] = a4.y;
        As[(acol + 2) * 128 + arow] = a4.z;
        As[(acol + 3) * 128 + arow] = a4.w;
        *(float4*)&Bs[brow * 128 + bcol] = b4;
        __syncthreads();
#pragma unroll
        for (int k = 0; k < 8; k++) {
            float a[8], b[8];
#pragma unroll
            for (int i = 0; i < 8; i++) a[i] = As[k * 128 + ty + 16 * i];
#pragma unroll
            for (int j = 0; j < 8; j++) b[j] = Bs[k * 128 + tx + 16 * j];
#pragma unroll
            for (int i = 0; i < 8; i++)
#pragma unroll
                for (int j = 0; j < 8; j++)
                    acc[i][j] = fmaf(a[i], b[j], acc[i][j]);
        }
    }

#pragma unroll
    for (int i = 0; i < 8; i++) {
        size_t r = (size_t)(row0 + ty + 16 * i);
#pragma unroll
        for (int j = 0; j < 8; j++)
            C[r * N + col0 + tx + 16 * j] = acc[i][j];
    }
}

// ---------------------------------------------------------------------------
// Local windowed attention with RoPE. One CTA per (window, head, batch).
// Q: 128x64 (this window), K/V: 256x64 (previous window ++ this window).
// ---------------------------------------------------------------------------
// Shared layout (floats):
//   phase 1: sQ [128][65] at 0 (8320), sKT [64][257] at 8320 (16448)
//   phase 2: sP [128][257] at 0 (32896)  -- overlaps dead sQ/sKT
//   always : sV [256][64] at 32896 (16384)
#define SMEM_FLOATS 49280
#define SMEM_BYTES  (SMEM_FLOATS * 4)

__global__ __launch_bounds__(256) void local_attn_kernel()
{
    extern __shared__ float sm[];
    float* sQ  = sm;             // [128][65]
    float* sKT = sm + 8320;      // [64][257]  (K transposed: [d][j])
    float* sP  = sm;             // [128][257]
    float* sV  = sm + 32896;     // [256][64]

    const int widx = blockIdx.x;
    const int h    = blockIdx.y;
    const int bi   = blockIdx.z;
    const int tid  = threadIdx.x;

    const int d   = tid & 31;    // 0..31 (rope half index)
    const int grp = tid >> 5;    // 0..7

    // inv_freq[d] = theta^(-d/32), accurate version (fast-math would inject
    // up to ~1e-5 rel err into angles up to 255 rad -> borderline vs 1e-3 tol)
    const float inv_freq = expf(-logf(10000.0f) * (float)d * (1.0f / 32.0f));
    const float scale = 0.125f;   // DH^-0.5

    // ---- load Q (+scale +RoPE, store [i][d] padded 65) ----
    const float* qbase = g_qkv + (size_t)(bi * NTOK + widx * WS) * QKVN + h * DH;
#pragma unroll 4
    for (int it = 0; it < 16; it++) {
        int i = grp + 8 * it;
        const float* p = qbase + (size_t)i * QKVN;
        float x1 = p[d], x2 = p[d + 32];
        float s, c;
        sincosf((float)(WS + i) * inv_freq, &s, &c);
        sQ[i * 65 + d]      = (x1 * c - x2 * s) * scale;
        sQ[i * 65 + d + 32] = (x2 * c + x1 * s) * scale;
    }
    // ---- load K (+RoPE, store transposed [d][j] padded 257) ----
    const float* kbase = g_qkv + (size_t)(bi * NTOK) * QKVN + DIM + h * DH;
#pragma unroll 4
    for (int it = 0; it < 32; it++) {
        int jj  = grp + 8 * it;
        int tok = (widx - 1) * WS + jj;
        float x1 = 0.f, x2 = 0.f;
        if (tok >= 0) {
            const float* p = kbase + (size_t)tok * QKVN;
            x1 = p[d]; x2 = p[d + 32];
        }
        float s, c;
        sincosf((float)jj * inv_freq, &s, &c);
        sKT[d * 257 + jj]        = x1 * c - x2 * s;
        sKT[(d + 32) * 257 + jj] = x2 * c + x1 * s;
    }
    // ---- load V (zero the padded rows: masked p==0, but 0*NaN would poison) ----
    const float* vbase = g_qkv + (size_t)(bi * NTOK) * QKVN + 2 * DIM + h * DH;
    for (int idx = tid; idx < 256 * 64; idx += 256) {
        int jj = idx >> 6, dd = idx & 63;
        int tok = (widx - 1) * WS + jj;
        sV[jj * 64 + dd] = (tok < 0) ? 0.f : vbase[(size_t)tok * QKVN + dd];
    }
    __syncthreads();

    // ---- S = Q @ K^T : thread (ty,tx) owns rows ty*8+i, cols tx+16*j ----
    const int tx = tid & 15;
    const int ty = tid >> 4;
    float acc[8][16];
#pragma unroll
    for (int i = 0; i < 8; i++)
#pragma unroll
        for (int j = 0; j < 16; j++) acc[i][j] = 0.f;

    for (int dd = 0; dd < 64; dd++) {
        float a[8], b[16];
#pragma unroll
        for (int i = 0; i < 8; i++) a[i] = sQ[(ty * 8 + i) * 65 + dd];
#pragma unroll
        for (int j = 0; j < 16; j++) b[j] = sKT[dd * 257 + tx + 16 * j];
#pragma unroll
        for (int i = 0; i < 8; i++)
#pragma unroll
            for (int j = 0; j < 16; j++)
                acc[i][j] = fmaf(a[i], b[j], acc[i][j]);
    }

    // ---- mask + row softmax (each row is spread across 16 consecutive lanes) ----
#pragma unroll
    for (int i = 0; i < 8; i++) {
        int r = ty * 8 + i;
        float mx = -1e30f;
#pragma unroll
        for (int j = 0; j < 16; j++) {
            int c = tx + 16 * j;
            bool keep = (c >= r) && (c <= r + WS) && (widx > 0 || c >= WS);
            if (!keep) acc[i][j] = -1e30f;
            mx = fmaxf(mx, acc[i][j]);
        }
#pragma unroll
        for (int m = 8; m >= 1; m >>= 1)
            mx = fmaxf(mx, __shfl_xor_sync(0xffffffffu, mx, m));
        float sum = 0.f;
#pragma unroll
        for (int j = 0; j < 16; j++) {
            acc[i][j] = expf(acc[i][j] - mx);   // masked -> exp(-1e30) == 0
            sum += acc[i][j];
        }
#pragma unroll
        for (int m = 8; m >= 1; m >>= 1)
            sum += __shfl_xor_sync(0xffffffffu, sum, m);
        float inv = 1.0f / sum;
#pragma unroll
        for (int j = 0; j < 16; j++) acc[i][j] *= inv;
    }

    __syncthreads();   // everyone done reading sQ/sKT before sP overwrites them
#pragma unroll
    for (int i = 0; i < 8; i++)
#pragma unroll
        for (int j = 0; j < 16; j++)
            sP[(ty * 8 + i) * 257 + tx + 16 * j] = acc[i][j];
    __syncthreads();

    // ---- O = P @ V : thread owns rows ty*8+i, dcols tx+16*j (j<4) ----
    float o[8][4];
#pragma unroll
    for (int i = 0; i < 8; i++)
#pragma unroll
        for (int j = 0; j < 4; j++) o[i][j] = 0.f;

    for (int c = 0; c < 256; c++) {
        float a[8], b[4];
#pragma unroll
        for (int i = 0; i < 8; i++) a[i] = sP[(ty * 8 + i) * 257 + c];
#pragma unroll
        for (int j = 0; j < 4; j++) b[j] = sV[c * 64 + tx + 16 * j];
#pragma unroll
        for (int i = 0; i < 8; i++)
#pragma unroll
            for (int j = 0; j < 4; j++)
                o[i][j] = fmaf(a[i], b[j], o[i][j]);
    }

    float* obase = g_attn + (size_t)(bi * NTOK + widx * WS) * DIM + h * DH;
#pragma unroll
    for (int i = 0; i < 8; i++)
#pragma unroll
        for (int j = 0; j < 4; j++)
            obase[(size_t)(ty * 8 + i) * DIM + tx + 16 * j] = o[i][j];
}

// ---------------------------------------------------------------------------
extern "C" void kernel_launch(void* const* d_in, const int* in_sizes, int n_in,
                              void* d_out, int out_size)
{
    const float* x     = (const float*)d_in[0];   // (4,4096,1024)
    const float* Wqkv  = (const float*)d_in[1];   // (1024,3072)
    const float* Wout  = (const float*)d_in[2];   // (1024,1024)
    float* out = (float*)d_out;                   // (4,4096,1024)

    float *qkv_ptr, *attn_ptr;
    cudaGetSymbolAddress((void**)&qkv_ptr, g_qkv);
    cudaGetSymbolAddress((void**)&attn_ptr, g_attn);

    cudaFuncSetAttribute(local_attn_kernel,
                         cudaFuncAttributeMaxDynamicSharedMemorySize, SMEM_BYTES);

    const int M = BATCH * NTOK;   // 16384

    // 1) qkv = x @ W_qkv
    sgemm128<<<dim3(QKVN / 128, M / 128), 256>>>(x, Wqkv, qkv_ptr, M, QKVN, DIM);

    // 2) local attention (RoPE + mask + softmax + PV), writes (b,n,h*dh)
    local_attn_kernel<<<dim3(NWIN, NHEAD, BATCH), 256, SMEM_BYTES>>>();

    // 3) out = attn @ W_out
    sgemm128<<<dim3(DIM / 128, M / 128), 256>>>(attn_ptr, Wout, out, M, DIM, DIM);
}

// round 5
// speedup vs baseline: 1.9658x; 1.9658x over previous
#include <cuda_runtime.h>
#include <cuda_bf16.h>
#include <math.h>
#include <stdint.h>

#define BATCH 4
#define NTOK  4096
#define DIM   1024
#define NHEAD 16
#define DH    64
#define WS    128
#define NWIN  32
#define QKVN  3072
#define MTOT  (BATCH * NTOK)   // 16384

// ---------------------------------------------------------------------------
// Scratch (static device globals: allocation-free, graph-capturable)
// ---------------------------------------------------------------------------
__device__ float         g_qkv [(size_t)MTOT * QKVN];      // f32 q|k|v
__device__ __nv_bfloat16 g_xh  [(size_t)MTOT * DIM];       // x split hi
__device__ __nv_bfloat16 g_xl  [(size_t)MTOT * DIM];       // x split lo
__device__ __nv_bfloat16 g_wqh [(size_t)QKVN * DIM];       // Wqkv^T hi [3072][1024]
__device__ __nv_bfloat16 g_wql [(size_t)QKVN * DIM];       // Wqkv^T lo
__device__ __nv_bfloat16 g_woh [(size_t)DIM * DIM];        // Wout^T hi [1024][1024]
__device__ __nv_bfloat16 g_wol [(size_t)DIM * DIM];        // Wout^T lo
__device__ __nv_bfloat16 g_ah  [(size_t)MTOT * DIM];       // attn out hi
__device__ __nv_bfloat16 g_al  [(size_t)MTOT * DIM];       // attn out lo

// ---------------------------------------------------------------------------
// Base-target (sm_103, no 'a') tensor-core primitives: mma.sync + ldmatrix +
// cp.async. tcgen05 is NOT available through this toolchain (PTX targets
// compute_103, which rejects all 'a'-gated features).
// ---------------------------------------------------------------------------
__device__ __forceinline__ uint32_t smem_u32(const void* p) {
    return (uint32_t)__cvta_generic_to_shared(p);
}

__device__ __forceinline__ void cp_async16(uint32_t saddr, const void* gaddr) {
    asm volatile("cp.async.cg.shared.global [%0], [%1], 16;" :: "r"(saddr), "l"(gaddr));
}
#define CP_COMMIT()  asm volatile("cp.async.commit_group;" ::: "memory")
#define CP_WAIT(N)   asm volatile("cp.async.wait_group %0;" :: "n"(N) : "memory")

__device__ __forceinline__ void ldm_x4(uint32_t* r, uint32_t addr) {
    asm volatile("ldmatrix.sync.aligned.m8n8.x4.shared.b16 {%0,%1,%2,%3}, [%4];"
                 : "=r"(r[0]), "=r"(r[1]), "=r"(r[2]), "=r"(r[3]) : "r"(addr));
}

__device__ __forceinline__ void mma16816(float* c, const uint32_t* a, const uint32_t* b) {
    asm volatile("mma.sync.aligned.m16n8k16.row.col.f32.bf16.bf16.f32 "
                 "{%0,%1,%2,%3}, {%4,%5,%6,%7}, {%8,%9}, {%0,%1,%2,%3};"
                 : "+f"(c[0]), "+f"(c[1]), "+f"(c[2]), "+f"(c[3])
                 : "r"(a[0]), "r"(a[1]), "r"(a[2]), "r"(a[3]), "r"(b[0]), "r"(b[1]));
}

// ---------------------------------------------------------------------------
// Prep: f32 -> (hi, lo) bf16 split, elementwise (4 elems/thread)
// ---------------------------------------------------------------------------
__global__ __launch_bounds__(256) void split_f32(const float* __restrict__ src,
                                                 __nv_bfloat16* __restrict__ hi,
                                                 __nv_bfloat16* __restrict__ lo, int n4)
{
    int i = blockIdx.x * 256 + threadIdx.x;
    if (i >= n4) return;
    float4 v = ((const float4*)src)[i];
    float a[4] = {v.x, v.y, v.z, v.w};
#pragma unroll
    for (int j = 0; j < 4; j++) {
        __nv_bfloat16 h = __float2bfloat16(a[j]);
        hi[i * 4 + j] = h;
        lo[i * 4 + j] = __float2bfloat16(a[j] - __bfloat162float(h));
    }
}

// ---------------------------------------------------------------------------
// Prep: W[K][N] f32 -> Wt[N][K] hi/lo bf16 (32x32 smem transpose)
// ---------------------------------------------------------------------------
__global__ __launch_bounds__(256) void transpose_split(const float* __restrict__ W,
                                                       __nv_bfloat16* __restrict__ Th,
                                                       __nv_bfloat16* __restrict__ Tl,
                                                       int K, int N)
{
    __shared__ float t[32][33];
    int n0 = blockIdx.x * 32, k0 = blockIdx.y * 32;
    int tx = threadIdx.x & 31, ty8 = threadIdx.x >> 5;   // 32 x 8
#pragma unroll
    for (int r = 0; r < 4; r++) {
        int ky = ty8 + r * 8;
        t[ky][tx] = W[(size_t)(k0 + ky) * N + n0 + tx];
    }
    __syncthreads();
#pragma unroll
    for (int r = 0; r < 4; r++) {
        int ny = ty8 + r * 8;
        float v = t[tx][ny];
        __nv_bfloat16 h = __float2bfloat16(v);
        Th[(size_t)(n0 + ny) * K + k0 + tx] = h;
        Tl[(size_t)(n0 + ny) * K + k0 + tx] = __float2bfloat16(v - __bfloat162float(h));
    }
}

// ---------------------------------------------------------------------------
// bf16x3 GEMM via mma.sync: C[M,N] = (Ah+Al)[M,K] @ (Bh+Bl)[N,K]^T
// CTA tile 128x128, K-chunk 32, 8 warps (each 64x32), 2-stage cp.async.
// Smem per stage: 4 arrays x [128 rows][40 bf16] (80B rows, conflict-free
// ldmatrix: 20-bank stride covers all 32 banks across 8 rows).
// ---------------------------------------------------------------------------
#define KC       32
#define ROWB     80                    // padded row bytes (32 bf16 + 8 pad)
#define ARR_B    (128 * ROWB)          // 10240 B per array
#define STAGE_B  (4 * ARR_B)           // 40960 B per stage
#define GSMEM_BYTES (2 * STAGE_B)      // 81920 B

__global__ __launch_bounds__(256) void gemm_bf16x3(
    const __nv_bfloat16* __restrict__ Ah, const __nv_bfloat16* __restrict__ Al,
    const __nv_bfloat16* __restrict__ Bh, const __nv_bfloat16* __restrict__ Bl,
    float* __restrict__ C, int M, int N, int K)
{
    extern __shared__ char sm[];
    const uint32_t sbase = smem_u32(sm);
    const int tid  = threadIdx.x;
    const int wid  = tid >> 5;
    const int lane = tid & 31;
    const int wr   = (wid >> 2) * 64;    // warp row offset in tile (0 / 64)
    const int wc   = (wid & 3) * 32;     // warp col offset (0/32/64/96)

    const int r0 = blockIdx.y * 128;
    const int c0 = blockIdx.x * 128;

    const __nv_bfloat16* gsrc[4] = {
        Ah + (size_t)r0 * K, Al + (size_t)r0 * K,
        Bh + (size_t)c0 * K, Bl + (size_t)c0 * K };

    // cp.async issue lambda: stage s, k-chunk kc. 512 16B segments per array.
    const int ldrow = tid >> 2;          // 0..63  (two passes of 64 rows)
    const int ldseg = tid & 3;           // 0..3

    auto issue = [&](int kc, int s) {
        const uint32_t stb = sbase + s * STAGE_B;
#pragma unroll
        for (int t = 0; t < 4; t++) {
#pragma unroll
            for (int half = 0; half < 2; half++) {
                int row = ldrow + half * 64;
                const void* g = gsrc[t] + (size_t)row * K + kc * KC + ldseg * 8;
                cp_async16(stb + t * ARR_B + row * ROWB + ldseg * 16, g);
            }
        }
    };

    float acc[4][4][4];
#pragma unroll
    for (int mt = 0; mt < 4; mt++)
#pragma unroll
        for (int nt = 0; nt < 4; nt++)
#pragma unroll
            for (int i = 0; i < 4; i++) acc[mt][nt][i] = 0.f;

    const int nchunk = K / KC;
    issue(0, 0);
    CP_COMMIT();

    for (int kc = 0; kc < nchunk; kc++) {
        const int s = kc & 1;
        if (kc + 1 < nchunk) {
            issue(kc + 1, s ^ 1);
            CP_COMMIT();
            CP_WAIT(1);
        } else {
            CP_WAIT(0);
        }
        __syncthreads();

        const uint32_t stb = sbase + s * STAGE_B;
        const uint32_t lrow16 = (lane & 15) * ROWB + (lane >> 4) * 16;

#pragma unroll
        for (int ks = 0; ks < 2; ks++) {
            const uint32_t ko = ks * 32;   // 16 bf16 = 32 bytes
            uint32_t ah[4][4], al_[4][4];
#pragma unroll
            for (int mt = 0; mt < 4; mt++) {
                uint32_t ra = (wr + mt * 16) * ROWB + ko + lrow16;
                ldm_x4(ah[mt],  stb + 0 * ARR_B + ra);
                ldm_x4(al_[mt], stb + 1 * ARR_B + ra);
            }
            uint32_t bh[4][2], bl[4][2];
#pragma unroll
            for (int nh = 0; nh < 2; nh++) {
                uint32_t rb = (wc + nh * 16) * ROWB + ko + lrow16;
                uint32_t r[4];
                ldm_x4(r, stb + 2 * ARR_B + rb);
                bh[nh * 2][0] = r[0]; bh[nh * 2][1] = r[2];
                bh[nh * 2 + 1][0] = r[1]; bh[nh * 2 + 1][1] = r[3];
                ldm_x4(r, stb + 3 * ARR_B + rb);
                bl[nh * 2][0] = r[0]; bl[nh * 2][1] = r[2];
                bl[nh * 2 + 1][0] = r[1]; bl[nh * 2 + 1][1] = r[3];
            }
#pragma unroll
            for (int mt = 0; mt < 4; mt++)
#pragma unroll
                for (int nt = 0; nt < 4; nt++) {
                    mma16816(acc[mt][nt], ah[mt],  bh[nt]);
                    mma16816(acc[mt][nt], ah[mt],  bl[nt]);
                    mma16816(acc[mt][nt], al_[mt], bh[nt]);
                }
        }
        __syncthreads();
    }

    // epilogue: f32 accumulators -> C
    const int gr = lane >> 2;
    const int gc = (lane & 3) * 2;
#pragma unroll
    for (int mt = 0; mt < 4; mt++) {
        int row = r0 + wr + mt * 16 + gr;
#pragma unroll
        for (int nt = 0; nt < 4; nt++) {
            int col = c0 + wc + nt * 8 + gc;
            *(float2*)&C[(size_t)row * N + col] =
                make_float2(acc[mt][nt][0], acc[mt][nt][1]);
            *(float2*)&C[(size_t)(row + 8) * N + col] =
                make_float2(acc[mt][nt][2], acc[mt][nt][3]);
        }
    }
}

// ---------------------------------------------------------------------------
// Local windowed attention with RoPE (fp32 SIMT). One CTA per (window, head, b).
// Epilogue writes bf16 hi/lo split directly (feeds out-proj GEMM).
// ---------------------------------------------------------------------------
#define SMEM_FLOATS 49280
#define SMEM_BYTES  (SMEM_FLOATS * 4)

__global__ __launch_bounds__(256) void local_attn_kernel()
{
    extern __shared__ float smf[];
    float* sQ  = smf;             // [128][65]
    float* sKT = smf + 8320;      // [64][257]
    float* sP  = smf;             // [128][257]
    float* sV  = smf + 32896;     // [256][64]

    const int widx = blockIdx.x;
    const int h    = blockIdx.y;
    const int bi   = blockIdx.z;
    const int tid  = threadIdx.x;
    const int d    = tid & 31;
    const int grp  = tid >> 5;

    const float inv_freq = expf(-logf(10000.0f) * (float)d * (1.0f / 32.0f));
    const float scale = 0.125f;

    const float* qbase = g_qkv + (size_t)(bi * NTOK + widx * WS) * QKVN + h * DH;
#pragma unroll 4
    for (int it = 0; it < 16; it++) {
        int i = grp + 8 * it;
        const float* p = qbase + (size_t)i * QKVN;
        float x1 = p[d], x2 = p[d + 32];
        float s, c;
        sincosf((float)(WS + i) * inv_freq, &s, &c);
        sQ[i * 65 + d]      = (x1 * c - x2 * s) * scale;
        sQ[i * 65 + d + 32] = (x2 * c + x1 * s) * scale;
    }
    const float* kbase = g_qkv + (size_t)(bi * NTOK) * QKVN + DIM + h * DH;
#pragma unroll 4
    for (int it = 0; it < 32; it++) {
        int jj  = grp + 8 * it;
        int tok = (widx - 1) * WS + jj;
        float x1 = 0.f, x2 = 0.f;
        if (tok >= 0) {
            const float* p = kbase + (size_t)tok * QKVN;
            x1 = p[d]; x2 = p[d + 32];
        }
        float s, c;
        sincosf((float)jj * inv_freq, &s, &c);
        sKT[d * 257 + jj]        = x1 * c - x2 * s;
        sKT[(d + 32) * 257 + jj] = x2 * c + x1 * s;
    }
    const float* vbase = g_qkv + (size_t)(bi * NTOK) * QKVN + 2 * DIM + h * DH;
    for (int idx = tid; idx < 256 * 64; idx += 256) {
        int jj = idx >> 6, dd = idx & 63;
        int tok = (widx - 1) * WS + jj;
        sV[jj * 64 + dd] = (tok < 0) ? 0.f : vbase[(size_t)tok * QKVN + dd];
    }
    __syncthreads();

    const int tx = tid & 15;
    const int ty = tid >> 4;
    float acc[8][16];
#pragma unroll
    for (int i = 0; i < 8; i++)
#pragma unroll
        for (int j = 0; j < 16; j++) acc[i][j] = 0.f;

    for (int dd = 0; dd < 64; dd++) {
        float a[8], b[16];
#pragma unroll
        for (int i = 0; i < 8; i++) a[i] = sQ[(ty * 8 + i) * 65 + dd];
#pragma unroll
        for (int j = 0; j < 16; j++) b[j] = sKT[dd * 257 + tx + 16 * j];
#pragma unroll
        for (int i = 0; i < 8; i++)
#pragma unroll
            for (int j = 0; j < 16; j++)
                acc[i][j] = fmaf(a[i], b[j], acc[i][j]);
    }

#pragma unroll
    for (int i = 0; i < 8; i++) {
        int r = ty * 8 + i;
        float mx = -1e30f;
#pragma unroll
        for (int j = 0; j < 16; j++) {
            int c = tx + 16 * j;
            bool keep = (c >= r) && (c <= r + WS) && (widx > 0 || c >= WS);
            if (!keep) acc[i][j] = -1e30f;
            mx = fmaxf(mx, acc[i][j]);
        }
#pragma unroll
        for (int m = 8; m >= 1; m >>= 1)
            mx = fmaxf(mx, __shfl_xor_sync(0xffffffffu, mx, m));
        float sum = 0.f;
#pragma unroll
        for (int j = 0; j < 16; j++) {
            acc[i][j] = expf(acc[i][j] - mx);
            sum += acc[i][j];
        }
#pragma unroll
        for (int m = 8; m >= 1; m >>= 1)
            sum += __shfl_xor_sync(0xffffffffu, sum, m);
        float inv = 1.0f / sum;
#pragma unroll
        for (int j = 0; j < 16; j++) acc[i][j] *= inv;
    }

    __syncthreads();
#pragma unroll
    for (int i = 0; i < 8; i++)
#pragma unroll
        for (int j = 0; j < 16; j++)
            sP[(ty * 8 + i) * 257 + tx + 16 * j] = acc[i][j];
    __syncthreads();

    float o[8][4];
#pragma unroll
    for (int i = 0; i < 8; i++)
#pragma unroll
        for (int j = 0; j < 4; j++) o[i][j] = 0.f;

    for (int c = 0; c < 256; c++) {
        float a[8], b[4];
#pragma unroll
        for (int i = 0; i < 8; i++) a[i] = sP[(ty * 8 + i) * 257 + c];
#pragma unroll
        for (int j = 0; j < 4; j++) b[j] = sV[c * 64 + tx + 16 * j];
#pragma unroll
        for (int i = 0; i < 8; i++)
#pragma unroll
            for (int j = 0; j < 4; j++)
                o[i][j] = fmaf(a[i], b[j], o[i][j]);
    }

    size_t obase = (size_t)(bi * NTOK + widx * WS) * DIM + h * DH;
#pragma unroll
    for (int i = 0; i < 8; i++)
#pragma unroll
        for (int j = 0; j < 4; j++) {
            float v = o[i][j];
            __nv_bfloat16 hv = __float2bfloat16(v);
            size_t idx = obase + (size_t)(ty * 8 + i) * DIM + tx + 16 * j;
            g_ah[idx] = hv;
            g_al[idx] = __float2bfloat16(v - __bfloat162float(hv));
        }
}

// ---------------------------------------------------------------------------
extern "C" void kernel_launch(void* const* d_in, const int* in_sizes, int n_in,
                              void* d_out, int out_size)
{
    const float* x    = (const float*)d_in[0];
    const float* Wqkv = (const float*)d_in[1];
    const float* Wout = (const float*)d_in[2];
    float* out = (float*)d_out;

    float *qkv_p;
    __nv_bfloat16 *xh, *xl, *wqh, *wql, *woh, *wol, *ah, *al;
    cudaGetSymbolAddress((void**)&qkv_p, g_qkv);
    cudaGetSymbolAddress((void**)&xh, g_xh);   cudaGetSymbolAddress((void**)&xl, g_xl);
    cudaGetSymbolAddress((void**)&wqh, g_wqh); cudaGetSymbolAddress((void**)&wql, g_wql);
    cudaGetSymbolAddress((void**)&woh, g_woh); cudaGetSymbolAddress((void**)&wol, g_wol);
    cudaGetSymbolAddress((void**)&ah, g_ah);   cudaGetSymbolAddress((void**)&al, g_al);

    cudaFuncSetAttribute(local_attn_kernel,
                         cudaFuncAttributeMaxDynamicSharedMemorySize, SMEM_BYTES);
    cudaFuncSetAttribute(gemm_bf16x3,
                         cudaFuncAttributeMaxDynamicSharedMemorySize, GSMEM_BYTES);

    // prep: split x; transpose+split weights
    split_f32<<<(MTOT * DIM / 4 + 255) / 256, 256>>>(x, xh, xl, MTOT * DIM / 4);
    transpose_split<<<dim3(QKVN / 32, DIM / 32), 256>>>(Wqkv, wqh, wql, DIM, QKVN);
    transpose_split<<<dim3(DIM / 32, DIM / 32), 256>>>(Wout, woh, wol, DIM, DIM);

    // 1) qkv = x @ Wqkv   (bf16x3 mma.sync)
    gemm_bf16x3<<<dim3(QKVN / 128, MTOT / 128), 256, GSMEM_BYTES>>>(
        xh, xl, wqh, wql, qkv_p, MTOT, QKVN, DIM);

    // 2) local attention (writes bf16 hi/lo)
    local_attn_kernel<<<dim3(NWIN, NHEAD, BATCH), 256, SMEM_BYTES>>>();

    // 3) out = attn @ Wout (bf16x3 mma.sync)
    gemm_bf16x3<<<dim3(DIM / 128, MTOT / 128), 256, GSMEM_BYTES>>>(
        ah, al, woh, wol, out, MTOT, DIM, DIM);
}

// round 6
// speedup vs baseline: 2.1379x; 1.0876x over previous
#include <cuda_runtime.h>
#include <cuda_bf16.h>
#include <math.h>
#include <stdint.h>

#define BATCH 4
#define NTOK  4096
#define DIM   1024
#define NHEAD 16
#define DH    64
#define WS    128
#define NWIN  32
#define QKVN  3072
#define MTOT  (BATCH * NTOK)   // 16384

// ---------------------------------------------------------------------------
// Scratch (static device globals: allocation-free, graph-capturable)
// ---------------------------------------------------------------------------
__device__ float         g_qkv [(size_t)MTOT * QKVN];      // f32 q|k|v
__device__ __nv_bfloat16 g_xh  [(size_t)MTOT * DIM];
__device__ __nv_bfloat16 g_xl  [(size_t)MTOT * DIM];
__device__ __nv_bfloat16 g_wqh [(size_t)QKVN * DIM];
__device__ __nv_bfloat16 g_wql [(size_t)QKVN * DIM];
__device__ __nv_bfloat16 g_woh [(size_t)DIM * DIM];
__device__ __nv_bfloat16 g_wol [(size_t)DIM * DIM];
__device__ __nv_bfloat16 g_ah  [(size_t)MTOT * DIM];
__device__ __nv_bfloat16 g_al  [(size_t)MTOT * DIM];

// ---------------------------------------------------------------------------
// Base-target primitives (compute_103 rejects tcgen05; mma.sync is legal)
// ---------------------------------------------------------------------------
__device__ __forceinline__ uint32_t smem_u32(const void* p) {
    return (uint32_t)__cvta_generic_to_shared(p);
}
__device__ __forceinline__ void cp_async16(uint32_t saddr, const void* gaddr) {
    asm volatile("cp.async.cg.shared.global [%0], [%1], 16;" :: "r"(saddr), "l"(gaddr));
}
#define CP_COMMIT()  asm volatile("cp.async.commit_group;" ::: "memory")
#define CP_WAIT(N)   asm volatile("cp.async.wait_group %0;" :: "n"(N) : "memory")

__device__ __forceinline__ void ldm_x4(uint32_t* r, uint32_t addr) {
    asm volatile("ldmatrix.sync.aligned.m8n8.x4.shared.b16 {%0,%1,%2,%3}, [%4];"
                 : "=r"(r[0]), "=r"(r[1]), "=r"(r[2]), "=r"(r[3]) : "r"(addr));
}
__device__ __forceinline__ void mma16816(float* c, const uint32_t* a, const uint32_t* b) {
    asm volatile("mma.sync.aligned.m16n8k16.row.col.f32.bf16.bf16.f32 "
                 "{%0,%1,%2,%3}, {%4,%5,%6,%7}, {%8,%9}, {%0,%1,%2,%3};"
                 : "+f"(c[0]), "+f"(c[1]), "+f"(c[2]), "+f"(c[3])
                 : "r"(a[0]), "r"(a[1]), "r"(a[2]), "r"(a[3]), "r"(b[0]), "r"(b[1]));
}

// ---------------------------------------------------------------------------
// Prep kernels
// ---------------------------------------------------------------------------
__global__ __launch_bounds__(256) void split_f32(const float* __restrict__ src,
                                                 __nv_bfloat16* __restrict__ hi,
                                                 __nv_bfloat16* __restrict__ lo, int n4)
{
    int i = blockIdx.x * 256 + threadIdx.x;
    if (i >= n4) return;
    float4 v = ((const float4*)src)[i];
    float a[4] = {v.x, v.y, v.z, v.w};
#pragma unroll
    for (int j = 0; j < 4; j++) {
        __nv_bfloat16 h = __float2bfloat16(a[j]);
        hi[i * 4 + j] = h;
        lo[i * 4 + j] = __float2bfloat16(a[j] - __bfloat162float(h));
    }
}

__global__ __launch_bounds__(256) void transpose_split(const float* __restrict__ W,
                                                       __nv_bfloat16* __restrict__ Th,
                                                       __nv_bfloat16* __restrict__ Tl,
                                                       int K, int N)
{
    __shared__ float t[32][33];
    int n0 = blockIdx.x * 32, k0 = blockIdx.y * 32;
    int tx = threadIdx.x & 31, ty8 = threadIdx.x >> 5;
#pragma unroll
    for (int r = 0; r < 4; r++) {
        int ky = ty8 + r * 8;
        t[ky][tx] = W[(size_t)(k0 + ky) * N + n0 + tx];
    }
    __syncthreads();
#pragma unroll
    for (int r = 0; r < 4; r++) {
        int ny = ty8 + r * 8;
        float v = t[tx][ny];
        __nv_bfloat16 h = __float2bfloat16(v);
        Th[(size_t)(n0 + ny) * K + k0 + tx] = h;
        Tl[(size_t)(n0 + ny) * K + k0 + tx] = __float2bfloat16(v - __bfloat162float(h));
    }
}

// ---------------------------------------------------------------------------
// bf16x3 GEMM: 128x256 CTA tile, 512 threads (16 warps, each 64x32),
// KC=32, 3-stage cp.async pipeline, ONE __syncthreads per chunk.
// Stage layout: Ah[128x80] Al[128x80] Bh[256x80] Bl[256x80] = 61440 B.
// ---------------------------------------------------------------------------
#define KC       32
#define ROWB     80
#define A_ARR    (128 * ROWB)          // 10240
#define B_ARR    (256 * ROWB)          // 20480
#define STAGE_B  (2 * A_ARR + 2 * B_ARR)  // 61440
#define GSMEM_BYTES (3 * STAGE_B)      // 184320

__global__ __launch_bounds__(512) void gemm_bf16x3(
    const __nv_bfloat16* __restrict__ Ah, const __nv_bfloat16* __restrict__ Al,
    const __nv_bfloat16* __restrict__ Bh, const __nv_bfloat16* __restrict__ Bl,
    float* __restrict__ C, int M, int N, int K)
{
    extern __shared__ char sm[];
    const uint32_t sbase = smem_u32(sm);
    const int tid  = threadIdx.x;
    const int wid  = tid >> 5;
    const int lane = tid & 31;
    const int wr   = (wid >> 3) * 64;    // 0 / 64
    const int wc   = (wid & 7) * 32;     // 0..224

    const int r0 = blockIdx.y * 128;
    const int c0 = blockIdx.x * 256;

    const __nv_bfloat16* asrc[2] = { Ah + (size_t)r0 * K, Al + (size_t)r0 * K };
    const __nv_bfloat16* bsrc[2] = { Bh + (size_t)c0 * K, Bl + (size_t)c0 * K };

    const int lrow = tid >> 2;           // 0..127
    const int lseg = tid & 3;            // 0..3

    auto issue = [&](int kc, int s) {
        const uint32_t stb = sbase + s * STAGE_B;
#pragma unroll
        for (int t = 0; t < 2; t++)
            cp_async16(stb + t * A_ARR + lrow * ROWB + lseg * 16,
                       asrc[t] + (size_t)lrow * K + kc * KC + lseg * 8);
#pragma unroll
        for (int t = 0; t < 2; t++)
#pragma unroll
            for (int half = 0; half < 2; half++) {
                int row = lrow + half * 128;
                cp_async16(stb + 2 * A_ARR + t * B_ARR + row * ROWB + lseg * 16,
                           bsrc[t] + (size_t)row * K + kc * KC + lseg * 8);
            }
    };

    float acc[4][4][4];
#pragma unroll
    for (int mt = 0; mt < 4; mt++)
#pragma unroll
        for (int nt = 0; nt < 4; nt++)
#pragma unroll
            for (int i = 0; i < 4; i++) acc[mt][nt][i] = 0.f;

    const int nchunk = K / KC;
    issue(0, 0); CP_COMMIT();
    issue(1, 1); CP_COMMIT();

    const uint32_t lrow16 = (lane & 15) * ROWB + (lane >> 4) * 16;

    for (int kc = 0; kc < nchunk; kc++) {
        CP_WAIT(1);
        __syncthreads();
        if (kc + 2 < nchunk) issue(kc + 2, (kc + 2) % 3);
        CP_COMMIT();

        const uint32_t stb = sbase + (kc % 3) * STAGE_B;
#pragma unroll
        for (int ks = 0; ks < 2; ks++) {
            const uint32_t ko = ks * 32;
            uint32_t ah[4][4], al_[4][4];
#pragma unroll
            for (int mt = 0; mt < 4; mt++) {
                uint32_t ra = (wr + mt * 16) * ROWB + ko + lrow16;
                ldm_x4(ah[mt],  stb + 0 * A_ARR + ra);
                ldm_x4(al_[mt], stb + 1 * A_ARR + ra);
            }
            uint32_t bh[4][2], bl[4][2];
#pragma unroll
            for (int nh = 0; nh < 2; nh++) {
                uint32_t rb = 2 * A_ARR + (wc + nh * 16) * ROWB + ko + lrow16;
                uint32_t r[4];
                ldm_x4(r, stb + rb);
                bh[nh * 2][0] = r[0]; bh[nh * 2][1] = r[2];
                bh[nh * 2 + 1][0] = r[1]; bh[nh * 2 + 1][1] = r[3];
                ldm_x4(r, stb + rb + B_ARR);
                bl[nh * 2][0] = r[0]; bl[nh * 2][1] = r[2];
                bl[nh * 2 + 1][0] = r[1]; bl[nh * 2 + 1][1] = r[3];
            }
#pragma unroll
            for (int mt = 0; mt < 4; mt++)
#pragma unroll
                for (int nt = 0; nt < 4; nt++) {
                    mma16816(acc[mt][nt], ah[mt],  bh[nt]);
                    mma16816(acc[mt][nt], ah[mt],  bl[nt]);
                    mma16816(acc[mt][nt], al_[mt], bh[nt]);
                }
        }
    }

    const int gr = lane >> 2;
    const int gc = (lane & 3) * 2;
#pragma unroll
    for (int mt = 0; mt < 4; mt++) {
        int row = r0 + wr + mt * 16 + gr;
#pragma unroll
        for (int nt = 0; nt < 4; nt++) {
            int col = c0 + wc + nt * 8 + gc;
            *(float2*)&C[(size_t)row * N + col] =
                make_float2(acc[mt][nt][0], acc[mt][nt][1]);
            *(float2*)&C[(size_t)(row + 8) * N + col] =
                make_float2(acc[mt][nt][2], acc[mt][nt][3]);
        }
    }
}

// ---------------------------------------------------------------------------
// Tensor-core local attention. One CTA (256 thr, 8 warps) per (window,head,b).
// S = QK^T via bf16x3 (rope'd hi/lo in smem), softmax in registers,
// P hi/lo -> smem (overlaps dead Q/K), PV via Ph*Vh + Ph*Vl + Pl*Vh.
// Warp w owns S rows 16w..16w+15 across all 256 cols.
// ---------------------------------------------------------------------------
#define QK_ROWB 144                    // 64 bf16 (128B) + 16 pad
#define PV_ROWB 528                    // 256 bf16 (512B) + 16 pad
#define OFF_QH  0
#define OFF_QL  18432                  // 128*144
#define OFF_KH  36864
#define OFF_KL  73728                  // +256*144
#define OFF_PH  0                      // overlaps Q/K after S phase
#define OFF_PL  67584                  // 128*528
#define OFF_VH  135168
#define OFF_VL  168960                 // +64*528
#define ASMEM_BYTES 202752

__device__ __forceinline__ void store_hl(char* base_h, char* base_l,
                                         uint32_t off, float v0, float v1) {
    __nv_bfloat162 h = __floats2bfloat162_rn(v0, v1);
    float r0 = v0 - __bfloat162float(h.x);
    float r1 = v1 - __bfloat162float(h.y);
    *(__nv_bfloat162*)(base_h + off) = h;
    *(__nv_bfloat162*)(base_l + off) = __floats2bfloat162_rn(r0, r1);
}

__global__ __launch_bounds__(256) void attn_mma_kernel()
{
    extern __shared__ char sm[];
    const uint32_t sb = smem_u32(sm);

    const int widx = blockIdx.x;
    const int h    = blockIdx.y;
    const int bi   = blockIdx.z;
    const int tid  = threadIdx.x;
    const int wid  = tid >> 5;       // 0..7
    const int lane = tid & 31;
    const int d    = tid & 31;       // rope half index for load phase
    const int grp  = tid >> 5;

    const float inv_freq = expf(-logf(10000.0f) * (float)d * (1.0f / 32.0f));
    const float scale = 0.125f;

    // ---- load Q (+scale +RoPE) -> bf16 hi/lo, rows [i][64], 144B rows ----
    const float* qbase = g_qkv + (size_t)(bi * NTOK + widx * WS) * QKVN + h * DH;
#pragma unroll 4
    for (int it = 0; it < 16; it++) {
        int i = grp + 8 * it;
        const float* p = qbase + (size_t)i * QKVN;
        float x1 = p[d], x2 = p[d + 32];
        float s, c;
        sincosf((float)(WS + i) * inv_freq, &s, &c);
        float v1 = (x1 * c - x2 * s) * scale;
        float v2 = (x2 * c + x1 * s) * scale;
        uint32_t row = i * QK_ROWB;
        *(__nv_bfloat16*)(sm + OFF_QH + row + d * 2)        = __float2bfloat16(v1);
        *(__nv_bfloat16*)(sm + OFF_QH + row + (d + 32) * 2) = __float2bfloat16(v2);
        float h1 = __bfloat162float(*(__nv_bfloat16*)(sm + OFF_QH + row + d * 2));
        float h2 = __bfloat162float(*(__nv_bfloat16*)(sm + OFF_QH + row + (d + 32) * 2));
        *(__nv_bfloat16*)(sm + OFF_QL + row + d * 2)        = __float2bfloat16(v1 - h1);
        *(__nv_bfloat16*)(sm + OFF_QL + row + (d + 32) * 2) = __float2bfloat16(v2 - h2);
    }
    // ---- load K (+RoPE) -> bf16 hi/lo, 256 rows ----
    const float* kbase = g_qkv + (size_t)(bi * NTOK) * QKVN + DIM + h * DH;
#pragma unroll 4
    for (int it = 0; it < 32; it++) {
        int jj  = grp + 8 * it;
        int tok = (widx - 1) * WS + jj;
        float x1 = 0.f, x2 = 0.f;
        if (tok >= 0) {
            const float* p = kbase + (size_t)tok * QKVN;
            x1 = p[d]; x2 = p[d + 32];
        }
        float s, c;
        sincosf((float)jj * inv_freq, &s, &c);
        float v1 = x1 * c - x2 * s;
        float v2 = x2 * c + x1 * s;
        uint32_t row = jj * QK_ROWB;
        __nv_bfloat16 b1 = __float2bfloat16(v1), b2 = __float2bfloat16(v2);
        *(__nv_bfloat16*)(sm + OFF_KH + row + d * 2)        = b1;
        *(__nv_bfloat16*)(sm + OFF_KH + row + (d + 32) * 2) = b2;
        *(__nv_bfloat16*)(sm + OFF_KL + row + d * 2)        = __float2bfloat16(v1 - __bfloat162float(b1));
        *(__nv_bfloat16*)(sm + OFF_KL + row + (d + 32) * 2) = __float2bfloat16(v2 - __bfloat162float(b2));
    }
    // ---- load V transposed: V^T[dd][jj], hi/lo, 64 rows x 528B ----
    const float* vbase = g_qkv + (size_t)(bi * NTOK) * QKVN + 2 * DIM + h * DH;
    for (int idx = tid; idx < 256 * 64; idx += 256) {
        int jj = idx >> 6, dd = idx & 63;
        int tok = (widx - 1) * WS + jj;
        float v = (tok < 0) ? 0.f : vbase[(size_t)tok * QKVN + dd];
        __nv_bfloat16 hv = __float2bfloat16(v);
        uint32_t off = dd * PV_ROWB + jj * 2;
        *(__nv_bfloat16*)(sm + OFF_VH + off) = hv;
        *(__nv_bfloat16*)(sm + OFF_VL + off) = __float2bfloat16(v - __bfloat162float(hv));
    }
    __syncthreads();

    // ---- S = Q K^T (bf16x3). acc[nt][4], nt=0..31 over 256 cols ----
    float acc[32][4];
#pragma unroll
    for (int nt = 0; nt < 32; nt++)
#pragma unroll
        for (int i = 0; i < 4; i++) acc[nt][i] = 0.f;

    const uint32_t lrq = (lane & 15) * QK_ROWB + (lane >> 4) * 16;
    const uint32_t lrp = (lane & 15) * PV_ROWB + (lane >> 4) * 16;

#pragma unroll
    for (int ks = 0; ks < 4; ks++) {
        const uint32_t ko = ks * 32;
        uint32_t ah[4], al_[4];
        ldm_x4(ah,  sb + OFF_QH + wid * 16 * QK_ROWB + ko + lrq);
        ldm_x4(al_, sb + OFF_QL + wid * 16 * QK_ROWB + ko + lrq);
#pragma unroll
        for (int nt2 = 0; nt2 < 16; nt2++) {
            uint32_t addr = sb + OFF_KH + nt2 * 16 * QK_ROWB + ko + lrq;
            uint32_t rh[4], rl[4];
            ldm_x4(rh, addr);
            ldm_x4(rl, addr + (OFF_KL - OFF_KH));
            uint32_t bh0[2] = {rh[0], rh[2]}, bh1[2] = {rh[1], rh[3]};
            uint32_t bl0[2] = {rl[0], rl[2]}, bl1[2] = {rl[1], rl[3]};
            mma16816(acc[2 * nt2],     ah, bh0);
            mma16816(acc[2 * nt2],     ah, bl0);
            mma16816(acc[2 * nt2],     al_, bh0);
            mma16816(acc[2 * nt2 + 1], ah, bh1);
            mma16816(acc[2 * nt2 + 1], ah, bl1);
            mma16816(acc[2 * nt2 + 1], al_, bh1);
        }
    }
    __syncthreads();   // all warps done reading Q/K before P overwrites

    // ---- mask + softmax in registers (rows within quads) ----
    const int q4 = lane & 3;
#pragma unroll
    for (int i01 = 0; i01 < 2; i01++) {
        int r = wid * 16 + (lane >> 2) + i01 * 8;
        float mx = -1e30f;
#pragma unroll
        for (int nt = 0; nt < 32; nt++)
#pragma unroll
            for (int e = 0; e < 2; e++) {
                int c = 8 * nt + 2 * q4 + e;
                bool keep = (c >= r) && (c <= r + WS) && (widx > 0 || c >= WS);
                float& v = acc[nt][i01 * 2 + e];
                if (!keep) v = -1e30f;
                mx = fmaxf(mx, v);
            }
        mx = fmaxf(mx, __shfl_xor_sync(0xffffffffu, mx, 1));
        mx = fmaxf(mx, __shfl_xor_sync(0xffffffffu, mx, 2));
        float sum = 0.f;
#pragma unroll
        for (int nt = 0; nt < 32; nt++)
#pragma unroll
            for (int e = 0; e < 2; e++) {
                float& v = acc[nt][i01 * 2 + e];
                v = expf(v - mx);
                sum += v;
            }
        sum += __shfl_xor_sync(0xffffffffu, sum, 1);
        sum += __shfl_xor_sync(0xffffffffu, sum, 2);
        float inv = 1.0f / sum;
#pragma unroll
        for (int nt = 0; nt < 32; nt++)
#pragma unroll
            for (int e = 0; e < 2; e++) acc[nt][i01 * 2 + e] *= inv;

        // store P row (hi/lo bf16 pairs: cols 8nt+2q, +1)
        uint32_t rowoff = (uint32_t)r * PV_ROWB;
#pragma unroll
        for (int nt = 0; nt < 32; nt++) {
            uint32_t off = rowoff + (8 * nt + 2 * q4) * 2;
            store_hl(sm + OFF_PH, sm + OFF_PL, off,
                     acc[nt][i01 * 2], acc[nt][i01 * 2 + 1]);
        }
    }
    __syncthreads();

    // ---- O = P V (bf16x3): 8 n-tiles (64 cols), 16 k-steps ----
    float o[8][4];
#pragma unroll
    for (int nt = 0; nt < 8; nt++)
#pragma unroll
        for (int i = 0; i < 4; i++) o[nt][i] = 0.f;

#pragma unroll
    for (int ks = 0; ks < 16; ks++) {
        const uint32_t ko = ks * 32;
        uint32_t ph[4], pl[4];
        uint32_t addrA = sb + OFF_PH + wid * 16 * PV_ROWB + ko + lrp;
        ldm_x4(ph, addrA);
        ldm_x4(pl, addrA + (OFF_PL - OFF_PH));
#pragma unroll
        for (int nt2 = 0; nt2 < 4; nt2++) {
            uint32_t addrB = sb + OFF_VH + nt2 * 16 * PV_ROWB + ko + lrp;
            uint32_t rh[4], rl[4];
            ldm_x4(rh, addrB);
            ldm_x4(rl, addrB + (OFF_VL - OFF_VH));
            uint32_t vh0[2] = {rh[0], rh[2]}, vh1[2] = {rh[1], rh[3]};
            uint32_t vl0[2] = {rl[0], rl[2]}, vl1[2] = {rl[1], rl[3]};
            mma16816(o[2 * nt2],     ph, vh0);
            mma16816(o[2 * nt2],     ph, vl0);
            mma16816(o[2 * nt2],     pl, vh0);
            mma16816(o[2 * nt2 + 1], ph, vh1);
            mma16816(o[2 * nt2 + 1], ph, vl1);
            mma16816(o[2 * nt2 + 1], pl, vh1);
        }
    }

    // ---- write out hi/lo bf16 (feeds out-proj GEMM) ----
    const int gr = lane >> 2;
#pragma unroll
    for (int i01 = 0; i01 < 2; i01++) {
        int row = widx * WS + wid * 16 + gr + i01 * 8;
        size_t base = (size_t)(bi * NTOK + row) * DIM + h * DH;
#pragma unroll
        for (int nt = 0; nt < 8; nt++) {
            int col = nt * 8 + 2 * q4;
            float v0 = o[nt][i01 * 2], v1 = o[nt][i01 * 2 + 1];
            __nv_bfloat162 hv = __floats2bfloat162_rn(v0, v1);
            __nv_bfloat162 lv = __floats2bfloat162_rn(v0 - __bfloat162float(hv.x),
                                                      v1 - __bfloat162float(hv.y));
            *(__nv_bfloat162*)&g_ah[base + col] = hv;
            *(__nv_bfloat162*)&g_al[base + col] = lv;
        }
    }
}

// ---------------------------------------------------------------------------
extern "C" void kernel_launch(void* const* d_in, const int* in_sizes, int n_in,
                              void* d_out, int out_size)
{
    const float* x    = (const float*)d_in[0];
    const float* Wqkv = (const float*)d_in[1];
    const float* Wout = (const float*)d_in[2];
    float* out = (float*)d_out;

    float *qkv_p;
    __nv_bfloat16 *xh, *xl, *wqh, *wql, *woh, *wol, *ah, *al;
    cudaGetSymbolAddress((void**)&qkv_p, g_qkv);
    cudaGetSymbolAddress((void**)&xh, g_xh);   cudaGetSymbolAddress((void**)&xl, g_xl);
    cudaGetSymbolAddress((void**)&wqh, g_wqh); cudaGetSymbolAddress((void**)&wql, g_wql);
    cudaGetSymbolAddress((void**)&woh, g_woh); cudaGetSymbolAddress((void**)&wol, g_wol);
    cudaGetSymbolAddress((void**)&ah, g_ah);   cudaGetSymbolAddress((void**)&al, g_al);

    cudaFuncSetAttribute(gemm_bf16x3,
                         cudaFuncAttributeMaxDynamicSharedMemorySize, GSMEM_BYTES);
    cudaFuncSetAttribute(attn_mma_kernel,
                         cudaFuncAttributeMaxDynamicSharedMemorySize, ASMEM_BYTES);

    split_f32<<<(MTOT * DIM / 4 + 255) / 256, 256>>>(x, xh, xl, MTOT * DIM / 4);
    transpose_split<<<dim3(QKVN / 32, DIM / 32), 256>>>(Wqkv, wqh, wql, DIM, QKVN);
    transpose_split<<<dim3(DIM / 32, DIM / 32), 256>>>(Wout, woh, wol, DIM, DIM);

    gemm_bf16x3<<<dim3(QKVN / 256, MTOT / 128), 512, GSMEM_BYTES>>>(
        xh, xl, wqh, wql, qkv_p, MTOT, QKVN, DIM);

    attn_mma_kernel<<<dim3(NWIN, NHEAD, BATCH), 256, ASMEM_BYTES>>>();

    gemm_bf16x3<<<dim3(DIM / 256, MTOT / 128), 512, GSMEM_BYTES>>>(
        ah, al, woh, wol, out, MTOT, DIM, DIM);
}

// round 7
// speedup vs baseline: 2.3630x; 1.1053x over previous
#include <cuda_runtime.h>
#include <cuda_bf16.h>
#include <math.h>
#include <stdint.h>

#define BATCH 4
#define NTOK  4096
#define DIM   1024
#define NHEAD 16
#define DH    64
#define WS    128
#define NWIN  32
#define QKVN  3072
#define MTOT  (BATCH * NTOK)   // 16384

// ---------------------------------------------------------------------------
// Scratch (static device globals: allocation-free, graph-capturable)
// ---------------------------------------------------------------------------
__device__ float         g_qkv [(size_t)MTOT * QKVN];      // f32 q|k|v
__device__ __nv_bfloat16 g_xh  [(size_t)MTOT * DIM];
__device__ __nv_bfloat16 g_xl  [(size_t)MTOT * DIM];
__device__ __nv_bfloat16 g_wqh [(size_t)QKVN * DIM];
__device__ __nv_bfloat16 g_wql [(size_t)QKVN * DIM];
__device__ __nv_bfloat16 g_woh [(size_t)DIM * DIM];
__device__ __nv_bfloat16 g_wol [(size_t)DIM * DIM];
__device__ __nv_bfloat16 g_ah  [(size_t)MTOT * DIM];
__device__ __nv_bfloat16 g_al  [(size_t)MTOT * DIM];
__device__ float2        g_rope[256 * 32];                 // (sin, cos) per (pos, d)

// ---------------------------------------------------------------------------
// Base-target primitives (compute_103 rejects tcgen05; mma.sync is legal)
// ---------------------------------------------------------------------------
__device__ __forceinline__ uint32_t smem_u32(const void* p) {
    return (uint32_t)__cvta_generic_to_shared(p);
}
__device__ __forceinline__ void cp_async16(uint32_t saddr, const void* gaddr) {
    asm volatile("cp.async.cg.shared.global [%0], [%1], 16;" :: "r"(saddr), "l"(gaddr));
}
#define CP_COMMIT()  asm volatile("cp.async.commit_group;" ::: "memory")
#define CP_WAIT(N)   asm volatile("cp.async.wait_group %0;" :: "n"(N) : "memory")

__device__ __forceinline__ void ldm_x4(uint32_t* r, uint32_t addr) {
    asm volatile("ldmatrix.sync.aligned.m8n8.x4.shared.b16 {%0,%1,%2,%3}, [%4];"
                 : "=r"(r[0]), "=r"(r[1]), "=r"(r[2]), "=r"(r[3]) : "r"(addr));
}
__device__ __forceinline__ void mma16816(float* c, const uint32_t* a, const uint32_t* b) {
    asm volatile("mma.sync.aligned.m16n8k16.row.col.f32.bf16.bf16.f32 "
                 "{%0,%1,%2,%3}, {%4,%5,%6,%7}, {%8,%9}, {%0,%1,%2,%3};"
                 : "+f"(c[0]), "+f"(c[1]), "+f"(c[2]), "+f"(c[3])
                 : "r"(a[0]), "r"(a[1]), "r"(a[2]), "r"(a[3]), "r"(b[0]), "r"(b[1]));
}

// ---------------------------------------------------------------------------
// Prep kernels
// ---------------------------------------------------------------------------
__global__ __launch_bounds__(256) void rope_table_kernel()
{
    int idx = blockIdx.x * 256 + threadIdx.x;   // 8192 entries
    if (idx >= 256 * 32) return;
    int j = idx >> 5, d = idx & 31;
    float inv_freq = expf(-logf(10000.0f) * (float)d * (1.0f / 32.0f));
    float s, c;
    sincosf((float)j * inv_freq, &s, &c);
    g_rope[idx] = make_float2(s, c);
}

__global__ __launch_bounds__(256) void split_f32(const float* __restrict__ src,
                                                 __nv_bfloat16* __restrict__ hi,
                                                 __nv_bfloat16* __restrict__ lo, int n4)
{
    int i = blockIdx.x * 256 + threadIdx.x;
    if (i >= n4) return;
    float4 v = ((const float4*)src)[i];
    float a[4] = {v.x, v.y, v.z, v.w};
#pragma unroll
    for (int j = 0; j < 4; j++) {
        __nv_bfloat16 h = __float2bfloat16(a[j]);
        hi[i * 4 + j] = h;
        lo[i * 4 + j] = __float2bfloat16(a[j] - __bfloat162float(h));
    }
}

__global__ __launch_bounds__(256) void transpose_split(const float* __restrict__ W,
                                                       __nv_bfloat16* __restrict__ Th,
                                                       __nv_bfloat16* __restrict__ Tl,
                                                       int K, int N)
{
    __shared__ float t[32][33];
    int n0 = blockIdx.x * 32, k0 = blockIdx.y * 32;
    int tx = threadIdx.x & 31, ty8 = threadIdx.x >> 5;
#pragma unroll
    for (int r = 0; r < 4; r++) {
        int ky = ty8 + r * 8;
        t[ky][tx] = W[(size_t)(k0 + ky) * N + n0 + tx];
    }
    __syncthreads();
#pragma unroll
    for (int r = 0; r < 4; r++) {
        int ny = ty8 + r * 8;
        float v = t[tx][ny];
        __nv_bfloat16 h = __float2bfloat16(v);
        Th[(size_t)(n0 + ny) * K + k0 + tx] = h;
        Tl[(size_t)(n0 + ny) * K + k0 + tx] = __float2bfloat16(v - __bfloat162float(h));
    }
}

// ---------------------------------------------------------------------------
// bf16x3 GEMM via mma.sync: 128x128 CTA tile, 256 threads (8 warps, 64x32),
// KC=32, 2-stage cp.async, __launch_bounds__(256,2) -> 2 CTAs/SM so one
// CTA's MMAs cover the other's barrier/issue bubbles.
// ---------------------------------------------------------------------------
#define KC       32
#define ROWB     80                    // 16B-aligned, 5x16B stride -> conflict-free
#define ARR_B    (128 * ROWB)          // 10240
#define STAGE_B  (4 * ARR_B)           // 40960
#define GSMEM_BYTES (2 * STAGE_B)      // 81920 (x2 CTAs = 160KB/SM, fits 228KB)

__global__ __launch_bounds__(256, 2) void gemm_bf16x3(
    const __nv_bfloat16* __restrict__ Ah, const __nv_bfloat16* __restrict__ Al,
    const __nv_bfloat16* __restrict__ Bh, const __nv_bfloat16* __restrict__ Bl,
    float* __restrict__ C, int M, int N, int K)
{
    extern __shared__ char sm[];
    const uint32_t sbase = smem_u32(sm);
    const int tid  = threadIdx.x;
    const int wid  = tid >> 5;
    const int lane = tid & 31;
    const int wr   = (wid >> 2) * 64;
    const int wc   = (wid & 3) * 32;

    const int r0 = blockIdx.y * 128;
    const int c0 = blockIdx.x * 128;

    const __nv_bfloat16* gsrc[4] = {
        Ah + (size_t)r0 * K, Al + (size_t)r0 * K,
        Bh + (size_t)c0 * K, Bl + (size_t)c0 * K };

    const int ldrow = tid >> 2;
    const int ldseg = tid & 3;

    auto issue = [&](int kc, int s) {
        const uint32_t stb = sbase + s * STAGE_B;
#pragma unroll
        for (int t = 0; t < 4; t++) {
#pragma unroll
            for (int half = 0; half < 2; half++) {
                int row = ldrow + half * 64;
                const void* g = gsrc[t] + (size_t)row * K + kc * KC + ldseg * 8;
                cp_async16(stb + t * ARR_B + row * ROWB + ldseg * 16, g);
            }
        }
    };

    float acc[4][4][4];
#pragma unroll
    for (int mt = 0; mt < 4; mt++)
#pragma unroll
        for (int nt = 0; nt < 4; nt++)
#pragma unroll
            for (int i = 0; i < 4; i++) acc[mt][nt][i] = 0.f;

    const int nchunk = K / KC;
    issue(0, 0);
    CP_COMMIT();

    for (int kc = 0; kc < nchunk; kc++) {
        const int s = kc & 1;
        if (kc + 1 < nchunk) {
            issue(kc + 1, s ^ 1);
            CP_COMMIT();
            CP_WAIT(1);
        } else {
            CP_WAIT(0);
        }
        __syncthreads();

        const uint32_t stb = sbase + s * STAGE_B;
        const uint32_t lrow16 = (lane & 15) * ROWB + (lane >> 4) * 16;

#pragma unroll
        for (int ks = 0; ks < 2; ks++) {
            const uint32_t ko = ks * 32;
            uint32_t ah[4][4], al_[4][4];
#pragma unroll
            for (int mt = 0; mt < 4; mt++) {
                uint32_t ra = (wr + mt * 16) * ROWB + ko + lrow16;
                ldm_x4(ah[mt],  stb + 0 * ARR_B + ra);
                ldm_x4(al_[mt], stb + 1 * ARR_B + ra);
            }
            uint32_t bh[4][2], bl[4][2];
#pragma unroll
            for (int nh = 0; nh < 2; nh++) {
                uint32_t rb = (wc + nh * 16) * ROWB + ko + lrow16;
                uint32_t r[4];
                ldm_x4(r, stb + 2 * ARR_B + rb);
                bh[nh * 2][0] = r[0]; bh[nh * 2][1] = r[2];
                bh[nh * 2 + 1][0] = r[1]; bh[nh * 2 + 1][1] = r[3];
                ldm_x4(r, stb + 3 * ARR_B + rb);
                bl[nh * 2][0] = r[0]; bl[nh * 2][1] = r[2];
                bl[nh * 2 + 1][0] = r[1]; bl[nh * 2 + 1][1] = r[3];
            }
#pragma unroll
            for (int mt = 0; mt < 4; mt++)
#pragma unroll
                for (int nt = 0; nt < 4; nt++) {
                    mma16816(acc[mt][nt], ah[mt],  bh[nt]);
                    mma16816(acc[mt][nt], ah[mt],  bl[nt]);
                    mma16816(acc[mt][nt], al_[mt], bh[nt]);
                }
        }
        __syncthreads();
    }

    const int gr = lane >> 2;
    const int gc = (lane & 3) * 2;
#pragma unroll
    for (int mt = 0; mt < 4; mt++) {
        int row = r0 + wr + mt * 16 + gr;
#pragma unroll
        for (int nt = 0; nt < 4; nt++) {
            int col = c0 + wc + nt * 8 + gc;
            *(float2*)&C[(size_t)row * N + col] =
                make_float2(acc[mt][nt][0], acc[mt][nt][1]);
            *(float2*)&C[(size_t)(row + 8) * N + col] =
                make_float2(acc[mt][nt][2], acc[mt][nt][3]);
        }
    }
}

// ---------------------------------------------------------------------------
// Tensor-core local attention (bf16x3 S and PV), RoPE from table, __expf softmax.
// One CTA (256 thr, 8 warps) per (window, head, batch).
// ---------------------------------------------------------------------------
#define QK_ROWB 144
#define PV_ROWB 528
#define OFF_QH  0
#define OFF_QL  18432
#define OFF_KH  36864
#define OFF_KL  73728
#define OFF_PH  0
#define OFF_PL  67584
#define OFF_VH  135168
#define OFF_VL  168960
#define ASMEM_BYTES 202752

__device__ __forceinline__ void store_hl(char* base_h, char* base_l,
                                         uint32_t off, float v0, float v1) {
    __nv_bfloat162 h = __floats2bfloat162_rn(v0, v1);
    float r0 = v0 - __bfloat162float(h.x);
    float r1 = v1 - __bfloat162float(h.y);
    *(__nv_bfloat162*)(base_h + off) = h;
    *(__nv_bfloat162*)(base_l + off) = __floats2bfloat162_rn(r0, r1);
}

__global__ __launch_bounds__(256) void attn_mma_kernel()
{
    extern __shared__ char sm[];
    const uint32_t sb = smem_u32(sm);

    const int widx = blockIdx.x;
    const int h    = blockIdx.y;
    const int bi   = blockIdx.z;
    const int tid  = threadIdx.x;
    const int wid  = tid >> 5;
    const int lane = tid & 31;
    const int d    = tid & 31;
    const int grp  = tid >> 5;

    const float scale = 0.125f;

    // ---- load Q (+scale +RoPE from table) -> bf16 hi/lo ----
    const float* qbase = g_qkv + (size_t)(bi * NTOK + widx * WS) * QKVN + h * DH;
#pragma unroll 4
    for (int it = 0; it < 16; it++) {
        int i = grp + 8 * it;
        const float* p = qbase + (size_t)i * QKVN;
        float x1 = p[d], x2 = p[d + 32];
        float2 sc = g_rope[(WS + i) * 32 + d];
        float v1 = (x1 * sc.y - x2 * sc.x) * scale;
        float v2 = (x2 * sc.y + x1 * sc.x) * scale;
        uint32_t row = i * QK_ROWB;
        __nv_bfloat16 b1 = __float2bfloat16(v1), b2 = __float2bfloat16(v2);
        *(__nv_bfloat16*)(sm + OFF_QH + row + d * 2)        = b1;
        *(__nv_bfloat16*)(sm + OFF_QH + row + (d + 32) * 2) = b2;
        *(__nv_bfloat16*)(sm + OFF_QL + row + d * 2)        = __float2bfloat16(v1 - __bfloat162float(b1));
        *(__nv_bfloat16*)(sm + OFF_QL + row + (d + 32) * 2) = __float2bfloat16(v2 - __bfloat162float(b2));
    }
    // ---- load K (+RoPE) ----
    const float* kbase = g_qkv + (size_t)(bi * NTOK) * QKVN + DIM + h * DH;
#pragma unroll 4
    for (int it = 0; it < 32; it++) {
        int jj  = grp + 8 * it;
        int tok = (widx - 1) * WS + jj;
        float x1 = 0.f, x2 = 0.f;
        if (tok >= 0) {
            const float* p = kbase + (size_t)tok * QKVN;
            x1 = p[d]; x2 = p[d + 32];
        }
        float2 sc = g_rope[jj * 32 + d];
        float v1 = x1 * sc.y - x2 * sc.x;
        float v2 = x2 * sc.y + x1 * sc.x;
        uint32_t row = jj * QK_ROWB;
        __nv_bfloat16 b1 = __float2bfloat16(v1), b2 = __float2bfloat16(v2);
        *(__nv_bfloat16*)(sm + OFF_KH + row + d * 2)        = b1;
        *(__nv_bfloat16*)(sm + OFF_KH + row + (d + 32) * 2) = b2;
        *(__nv_bfloat16*)(sm + OFF_KL + row + d * 2)        = __float2bfloat16(v1 - __bfloat162float(b1));
        *(__nv_bfloat16*)(sm + OFF_KL + row + (d + 32) * 2) = __float2bfloat16(v2 - __bfloat162float(b2));
    }
    // ---- load V transposed hi/lo ----
    const float* vbase = g_qkv + (size_t)(bi * NTOK) * QKVN + 2 * DIM + h * DH;
    for (int idx = tid; idx < 256 * 64; idx += 256) {
        int jj = idx >> 6, dd = idx & 63;
        int tok = (widx - 1) * WS + jj;
        float v = (tok < 0) ? 0.f : vbase[(size_t)tok * QKVN + dd];
        __nv_bfloat16 hv = __float2bfloat16(v);
        uint32_t off = dd * PV_ROWB + jj * 2;
        *(__nv_bfloat16*)(sm + OFF_VH + off) = hv;
        *(__nv_bfloat16*)(sm + OFF_VL + off) = __float2bfloat16(v - __bfloat162float(hv));
    }
    __syncthreads();

    // ---- S = Q K^T (bf16x3) ----
    float acc[32][4];
#pragma unroll
    for (int nt = 0; nt < 32; nt++)
#pragma unroll
        for (int i = 0; i < 4; i++) acc[nt][i] = 0.f;

    const uint32_t lrq = (lane & 15) * QK_ROWB + (lane >> 4) * 16;
    const uint32_t lrp = (lane & 15) * PV_ROWB + (lane >> 4) * 16;

#pragma unroll
    for (int ks = 0; ks < 4; ks++) {
        const uint32_t ko = ks * 32;
        uint32_t ah[4], al_[4];
        ldm_x4(ah,  sb + OFF_QH + wid * 16 * QK_ROWB + ko + lrq);
        ldm_x4(al_, sb + OFF_QL + wid * 16 * QK_ROWB + ko + lrq);
#pragma unroll
        for (int nt2 = 0; nt2 < 16; nt2++) {
            uint32_t addr = sb + OFF_KH + nt2 * 16 * QK_ROWB + ko + lrq;
            uint32_t rh[4], rl[4];
            ldm_x4(rh, addr);
            ldm_x4(rl, addr + (OFF_KL - OFF_KH));
            uint32_t bh0[2] = {rh[0], rh[2]}, bh1[2] = {rh[1], rh[3]};
            uint32_t bl0[2] = {rl[0], rl[2]}, bl1[2] = {rl[1], rl[3]};
            mma16816(acc[2 * nt2],     ah, bh0);
            mma16816(acc[2 * nt2],     ah, bl0);
            mma16816(acc[2 * nt2],     al_, bh0);
            mma16816(acc[2 * nt2 + 1], ah, bh1);
            mma16816(acc[2 * nt2 + 1], ah, bl1);
            mma16816(acc[2 * nt2 + 1], al_, bh1);
        }
    }
    __syncthreads();

    // ---- mask + softmax (registers, quad shuffles), P -> smem hi/lo ----
    const int q4 = lane & 3;
#pragma unroll
    for (int i01 = 0; i01 < 2; i01++) {
        int r = wid * 16 + (lane >> 2) + i01 * 8;
        float mx = -1e30f;
#pragma unroll
        for (int nt = 0; nt < 32; nt++)
#pragma unroll
            for (int e = 0; e < 2; e++) {
                int c = 8 * nt + 2 * q4 + e;
                bool keep = (c >= r) && (c <= r + WS) && (widx > 0 || c >= WS);
                float& v = acc[nt][i01 * 2 + e];
                if (!keep) v = -1e30f;
                mx = fmaxf(mx, v);
            }
        mx = fmaxf(mx, __shfl_xor_sync(0xffffffffu, mx, 1));
        mx = fmaxf(mx, __shfl_xor_sync(0xffffffffu, mx, 2));
        float sum = 0.f;
#pragma unroll
        for (int nt = 0; nt < 32; nt++)
#pragma unroll
            for (int e = 0; e < 2; e++) {
                float& v = acc[nt][i01 * 2 + e];
                v = __expf(v - mx);
                sum += v;
            }
        sum += __shfl_xor_sync(0xffffffffu, sum, 1);
        sum += __shfl_xor_sync(0xffffffffu, sum, 2);
        float inv = 1.0f / sum;
#pragma unroll
        for (int nt = 0; nt < 32; nt++)
#pragma unroll
            for (int e = 0; e < 2; e++) acc[nt][i01 * 2 + e] *= inv;

        uint32_t rowoff = (uint32_t)r * PV_ROWB;
#pragma unroll
        for (int nt = 0; nt < 32; nt++) {
            uint32_t off = rowoff + (8 * nt + 2 * q4) * 2;
            store_hl(sm + OFF_PH, sm + OFF_PL, off,
                     acc[nt][i01 * 2], acc[nt][i01 * 2 + 1]);
        }
    }
    __syncthreads();

    // ---- O = P V (bf16x3) ----
    float o[8][4];
#pragma unroll
    for (int nt = 0; nt < 8; nt++)
#pragma unroll
        for (int i = 0; i < 4; i++) o[nt][i] = 0.f;

#pragma unroll
    for (int ks = 0; ks < 16; ks++) {
        const uint32_t ko = ks * 32;
        uint32_t ph[4], pl[4];
        uint32_t addrA = sb + OFF_PH + wid * 16 * PV_ROWB + ko + lrp;
        ldm_x4(ph, addrA);
        ldm_x4(pl, addrA + (OFF_PL - OFF_PH));
#pragma unroll
        for (int nt2 = 0; nt2 < 4; nt2++) {
            uint32_t addrB = sb + OFF_VH + nt2 * 16 * PV_ROWB + ko + lrp;
            uint32_t rh[4], rl[4];
            ldm_x4(rh, addrB);
            ldm_x4(rl, addrB + (OFF_VL - OFF_VH));
            uint32_t vh0[2] = {rh[0], rh[2]}, vh1[2] = {rh[1], rh[3]};
            uint32_t vl0[2] = {rl[0], rl[2]}, vl1[2] = {rl[1], rl[3]};
            mma16816(o[2 * nt2],     ph, vh0);
            mma16816(o[2 * nt2],     ph, vl0);
            mma16816(o[2 * nt2],     pl, vh0);
            mma16816(o[2 * nt2 + 1], ph, vh1);
            mma16816(o[2 * nt2 + 1], ph, vl1);
            mma16816(o[2 * nt2 + 1], pl, vh1);
        }
    }

    const int gr = lane >> 2;
#pragma unroll
    for (int i01 = 0; i01 < 2; i01++) {
        int row = widx * WS + wid * 16 + gr + i01 * 8;
        size_t base = (size_t)(bi * NTOK + row) * DIM + h * DH;
#pragma unroll
        for (int nt = 0; nt < 8; nt++) {
            int col = nt * 8 + 2 * q4;
            float v0 = o[nt][i01 * 2], v1 = o[nt][i01 * 2 + 1];
            __nv_bfloat162 hv = __floats2bfloat162_rn(v0, v1);
            __nv_bfloat162 lv = __floats2bfloat162_rn(v0 - __bfloat162float(hv.x),
                                                      v1 - __bfloat162float(hv.y));
            *(__nv_bfloat162*)&g_ah[base + col] = hv;
            *(__nv_bfloat162*)&g_al[base + col] = lv;
        }
    }
}

// ---------------------------------------------------------------------------
extern "C" void kernel_launch(void* const* d_in, const int* in_sizes, int n_in,
                              void* d_out, int out_size)
{
    const float* x    = (const float*)d_in[0];
    const float* Wqkv = (const float*)d_in[1];
    const float* Wout = (const float*)d_in[2];
    float* out = (float*)d_out;

    float *qkv_p;
    __nv_bfloat16 *xh, *xl, *wqh, *wql, *woh, *wol, *ah, *al;
    cudaGetSymbolAddress((void**)&qkv_p, g_qkv);
    cudaGetSymbolAddress((void**)&xh, g_xh);   cudaGetSymbolAddress((void**)&xl, g_xl);
    cudaGetSymbolAddress((void**)&wqh, g_wqh); cudaGetSymbolAddress((void**)&wql, g_wql);
    cudaGetSymbolAddress((void**)&woh, g_woh); cudaGetSymbolAddress((void**)&wol, g_wol);
    cudaGetSymbolAddress((void**)&ah, g_ah);   cudaGetSymbolAddress((void**)&al, g_al);

    cudaFuncSetAttribute(gemm_bf16x3,
                         cudaFuncAttributeMaxDynamicSharedMemorySize, GSMEM_BYTES);
    cudaFuncSetAttribute(attn_mma_kernel,
                         cudaFuncAttributeMaxDynamicSharedMemorySize, ASMEM_BYTES);

    rope_table_kernel<<<32, 256>>>();
    split_f32<<<(MTOT * DIM / 4 + 255) / 256, 256>>>(x, xh, xl, MTOT * DIM / 4);
    transpose_split<<<dim3(QKVN / 32, DIM / 32), 256>>>(Wqkv, wqh, wql, DIM, QKVN);
    transpose_split<<<dim3(DIM / 32, DIM / 32), 256>>>(Wout, woh, wol, DIM, DIM);

    gemm_bf16x3<<<dim3(QKVN / 128, MTOT / 128), 256, GSMEM_BYTES>>>(
        xh, xl, wqh, wql, qkv_p, MTOT, QKVN, DIM);

    attn_mma_kernel<<<dim3(NWIN, NHEAD, BATCH), 256, ASMEM_BYTES>>>();

    gemm_bf16x3<<<dim3(DIM / 128, MTOT / 128), 256, GSMEM_BYTES>>>(
        ah, al, woh, wol, out, MTOT, DIM, DIM);
}

// round 8
// speedup vs baseline: 2.4515x; 1.0374x over previous
#include <cuda_runtime.h>
#include <cuda_bf16.h>
#include <math.h>
#include <stdint.h>

#define BATCH 4
#define NTOK  4096
#define DIM   1024
#define NHEAD 16
#define DH    64
#define WS    128
#define NWIN  32
#define QKVN  3072
#define MTOT  (BATCH * NTOK)   // 16384

// ---------------------------------------------------------------------------
// Scratch (static device globals: allocation-free, graph-capturable)
// ---------------------------------------------------------------------------
__device__ float         g_qkv [(size_t)MTOT * QKVN];      // f32 q|k|v
__device__ __nv_bfloat16 g_xh  [(size_t)MTOT * DIM];
__device__ __nv_bfloat16 g_xl  [(size_t)MTOT * DIM];
__device__ __nv_bfloat16 g_wqh [(size_t)QKVN * DIM];
__device__ __nv_bfloat16 g_wql [(size_t)QKVN * DIM];
__device__ __nv_bfloat16 g_woh [(size_t)DIM * DIM];
__device__ __nv_bfloat16 g_wol [(size_t)DIM * DIM];
__device__ __nv_bfloat16 g_ah  [(size_t)MTOT * DIM];
__device__ __nv_bfloat16 g_al  [(size_t)MTOT * DIM];
__device__ float2        g_rope[256 * 32];                 // (sin, cos) per (pos, d)

// ---------------------------------------------------------------------------
// Base-target primitives (compute_103 rejects tcgen05; mma.sync is legal)
// ---------------------------------------------------------------------------
__device__ __forceinline__ uint32_t smem_u32(const void* p) {
    return (uint32_t)__cvta_generic_to_shared(p);
}
__device__ __forceinline__ void cp_async16(uint32_t saddr, const void* gaddr) {
    asm volatile("cp.async.cg.shared.global [%0], [%1], 16;" :: "r"(saddr), "l"(gaddr));
}
#define CP_COMMIT()  asm volatile("cp.async.commit_group;" ::: "memory")
#define CP_WAIT(N)   asm volatile("cp.async.wait_group %0;" :: "n"(N) : "memory")

__device__ __forceinline__ void ldm_x4(uint32_t* r, uint32_t addr) {
    asm volatile("ldmatrix.sync.aligned.m8n8.x4.shared.b16 {%0,%1,%2,%3}, [%4];"
                 : "=r"(r[0]), "=r"(r[1]), "=r"(r[2]), "=r"(r[3]) : "r"(addr));
}
__device__ __forceinline__ void mma16816(float* c, const uint32_t* a, const uint32_t* b) {
    asm volatile("mma.sync.aligned.m16n8k16.row.col.f32.bf16.bf16.f32 "
                 "{%0,%1,%2,%3}, {%4,%5,%6,%7}, {%8,%9}, {%0,%1,%2,%3};"
                 : "+f"(c[0]), "+f"(c[1]), "+f"(c[2]), "+f"(c[3])
                 : "r"(a[0]), "r"(a[1]), "r"(a[2]), "r"(a[3]), "r"(b[0]), "r"(b[1]));
}

// ---------------------------------------------------------------------------
// Prep kernels
// ---------------------------------------------------------------------------
__global__ __launch_bounds__(256) void rope_table_kernel()
{
    int idx = blockIdx.x * 256 + threadIdx.x;   // 8192 entries
    if (idx >= 256 * 32) return;
    int j = idx >> 5, d = idx & 31;
    float inv_freq = expf(-logf(10000.0f) * (float)d * (1.0f / 32.0f));
    float s, c;
    sincosf((float)j * inv_freq, &s, &c);
    g_rope[idx] = make_float2(s, c);
}

__global__ __launch_bounds__(256) void split_f32(const float* __restrict__ src,
                                                 __nv_bfloat16* __restrict__ hi,
                                                 __nv_bfloat16* __restrict__ lo, int n4)
{
    int i = blockIdx.x * 256 + threadIdx.x;
    if (i >= n4) return;
    float4 v = ((const float4*)src)[i];
    float a[4] = {v.x, v.y, v.z, v.w};
#pragma unroll
    for (int j = 0; j < 4; j++) {
        __nv_bfloat16 h = __float2bfloat16(a[j]);
        hi[i * 4 + j] = h;
        lo[i * 4 + j] = __float2bfloat16(a[j] - __bfloat162float(h));
    }
}

__global__ __launch_bounds__(256) void transpose_split(const float* __restrict__ W,
                                                       __nv_bfloat16* __restrict__ Th,
                                                       __nv_bfloat16* __restrict__ Tl,
                                                       int K, int N)
{
    __shared__ float t[32][33];
    int n0 = blockIdx.x * 32, k0 = blockIdx.y * 32;
    int tx = threadIdx.x & 31, ty8 = threadIdx.x >> 5;
#pragma unroll
    for (int r = 0; r < 4; r++) {
        int ky = ty8 + r * 8;
        t[ky][tx] = W[(size_t)(k0 + ky) * N + n0 + tx];
    }
    __syncthreads();
#pragma unroll
    for (int r = 0; r < 4; r++) {
        int ny = ty8 + r * 8;
        float v = t[tx][ny];
        __nv_bfloat16 h = __float2bfloat16(v);
        Th[(size_t)(n0 + ny) * K + k0 + tx] = h;
        Tl[(size_t)(n0 + ny) * K + k0 + tx] = __float2bfloat16(v - __bfloat162float(h));
    }
}

// ---------------------------------------------------------------------------
// bf16x3 GEMM via mma.sync: 128x128 CTA tile, 256 threads (8 warps, 64x32),
// KC=32, 2-stage cp.async, 2 CTAs/SM (known-good round-7 config).
// ---------------------------------------------------------------------------
#define KC       32
#define ROWB     80
#define ARR_B    (128 * ROWB)          // 10240
#define STAGE_B  (4 * ARR_B)           // 40960
#define GSMEM_BYTES (2 * STAGE_B)      // 81920

__global__ __launch_bounds__(256, 2) void gemm_bf16x3(
    const __nv_bfloat16* __restrict__ Ah, const __nv_bfloat16* __restrict__ Al,
    const __nv_bfloat16* __restrict__ Bh, const __nv_bfloat16* __restrict__ Bl,
    float* __restrict__ C, int M, int N, int K)
{
    extern __shared__ char sm[];
    const uint32_t sbase = smem_u32(sm);
    const int tid  = threadIdx.x;
    const int wid  = tid >> 5;
    const int lane = tid & 31;
    const int wr   = (wid >> 2) * 64;
    const int wc   = (wid & 3) * 32;

    const int r0 = blockIdx.y * 128;
    const int c0 = blockIdx.x * 128;

    const __nv_bfloat16* gsrc[4] = {
        Ah + (size_t)r0 * K, Al + (size_t)r0 * K,
        Bh + (size_t)c0 * K, Bl + (size_t)c0 * K };

    const int ldrow = tid >> 2;
    const int ldseg = tid & 3;

    auto issue = [&](int kc, int s) {
        const uint32_t stb = sbase + s * STAGE_B;
#pragma unroll
        for (int t = 0; t < 4; t++) {
#pragma unroll
            for (int half = 0; half < 2; half++) {
                int row = ldrow + half * 64;
                const void* g = gsrc[t] + (size_t)row * K + kc * KC + ldseg * 8;
                cp_async16(stb + t * ARR_B + row * ROWB + ldseg * 16, g);
            }
        }
    };

    float acc[4][4][4];
#pragma unroll
    for (int mt = 0; mt < 4; mt++)
#pragma unroll
        for (int nt = 0; nt < 4; nt++)
#pragma unroll
            for (int i = 0; i < 4; i++) acc[mt][nt][i] = 0.f;

    const int nchunk = K / KC;
    issue(0, 0);
    CP_COMMIT();

    for (int kc = 0; kc < nchunk; kc++) {
        const int s = kc & 1;
        if (kc + 1 < nchunk) {
            issue(kc + 1, s ^ 1);
            CP_COMMIT();
            CP_WAIT(1);
        } else {
            CP_WAIT(0);
        }
        __syncthreads();

        const uint32_t stb = sbase + s * STAGE_B;
        const uint32_t lrow16 = (lane & 15) * ROWB + (lane >> 4) * 16;

#pragma unroll
        for (int ks = 0; ks < 2; ks++) {
            const uint32_t ko = ks * 32;
            uint32_t ah[4][4], al_[4][4];
#pragma unroll
            for (int mt = 0; mt < 4; mt++) {
                uint32_t ra = (wr + mt * 16) * ROWB + ko + lrow16;
                ldm_x4(ah[mt],  stb + 0 * ARR_B + ra);
                ldm_x4(al_[mt], stb + 1 * ARR_B + ra);
            }
            uint32_t bh[4][2], bl[4][2];
#pragma unroll
            for (int nh = 0; nh < 2; nh++) {
                uint32_t rb = (wc + nh * 16) * ROWB + ko + lrow16;
                uint32_t r[4];
                ldm_x4(r, stb + 2 * ARR_B + rb);
                bh[nh * 2][0] = r[0]; bh[nh * 2][1] = r[2];
                bh[nh * 2 + 1][0] = r[1]; bh[nh * 2 + 1][1] = r[3];
                ldm_x4(r, stb + 3 * ARR_B + rb);
                bl[nh * 2][0] = r[0]; bl[nh * 2][1] = r[2];
                bl[nh * 2 + 1][0] = r[1]; bl[nh * 2 + 1][1] = r[3];
            }
#pragma unroll
            for (int mt = 0; mt < 4; mt++)
#pragma unroll
                for (int nt = 0; nt < 4; nt++) {
                    mma16816(acc[mt][nt], ah[mt],  bh[nt]);
                    mma16816(acc[mt][nt], ah[mt],  bl[nt]);
                    mma16816(acc[mt][nt], al_[mt], bh[nt]);
                }
        }
        __syncthreads();
    }

    const int gr = lane >> 2;
    const int gc = (lane & 3) * 2;
#pragma unroll
    for (int mt = 0; mt < 4; mt++) {
        int row = r0 + wr + mt * 16 + gr;
#pragma unroll
        for (int nt = 0; nt < 4; nt++) {
            int col = c0 + wc + nt * 8 + gc;
            *(float2*)&C[(size_t)row * N + col] =
                make_float2(acc[mt][nt][0], acc[mt][nt][1]);
            *(float2*)&C[(size_t)(row + 8) * N + col] =
                make_float2(acc[mt][nt][2], acc[mt][nt][3]);
        }
    }
}

// ---------------------------------------------------------------------------
// Tensor-core local attention, MASK-AWARE: warp w (rows 16w..16w+15) only
// touches columns [16w, 16w+143] (the union of each row's valid [r, r+128]).
// S: 9 of 16 K-tiles; softmax/P: 18 of 32 8-col tiles; PV: 9 of 16 k-steps.
// ---------------------------------------------------------------------------
#define QK_ROWB 144
#define PV_ROWB 528
#define OFF_QH  0
#define OFF_QL  18432
#define OFF_KH  36864
#define OFF_KL  73728
#define OFF_PH  0
#define OFF_PL  67584
#define OFF_VH  135168
#define OFF_VL  168960
#define ASMEM_BYTES 202752

__device__ __forceinline__ void store_hl(char* base_h, char* base_l,
                                         uint32_t off, float v0, float v1) {
    __nv_bfloat162 h = __floats2bfloat162_rn(v0, v1);
    float r0 = v0 - __bfloat162float(h.x);
    float r1 = v1 - __bfloat162float(h.y);
    *(__nv_bfloat162*)(base_h + off) = h;
    *(__nv_bfloat162*)(base_l + off) = __floats2bfloat162_rn(r0, r1);
}

__global__ __launch_bounds__(256) void attn_mma_kernel()
{
    extern __shared__ char sm[];
    const uint32_t sb = smem_u32(sm);

    const int widx = blockIdx.x;
    const int h    = blockIdx.y;
    const int bi   = blockIdx.z;
    const int tid  = threadIdx.x;
    const int wid  = tid >> 5;
    const int lane = tid & 31;
    const int d    = tid & 31;
    const int grp  = tid >> 5;

    const float scale = 0.125f;

    // ---- load Q (+scale +RoPE from table) -> bf16 hi/lo ----
    const float* qbase = g_qkv + (size_t)(bi * NTOK + widx * WS) * QKVN + h * DH;
#pragma unroll 4
    for (int it = 0; it < 16; it++) {
        int i = grp + 8 * it;
        const float* p = qbase + (size_t)i * QKVN;
        float x1 = p[d], x2 = p[d + 32];
        float2 sc = g_rope[(WS + i) * 32 + d];
        float v1 = (x1 * sc.y - x2 * sc.x) * scale;
        float v2 = (x2 * sc.y + x1 * sc.x) * scale;
        uint32_t row = i * QK_ROWB;
        __nv_bfloat16 b1 = __float2bfloat16(v1), b2 = __float2bfloat16(v2);
        *(__nv_bfloat16*)(sm + OFF_QH + row + d * 2)        = b1;
        *(__nv_bfloat16*)(sm + OFF_QH + row + (d + 32) * 2) = b2;
        *(__nv_bfloat16*)(sm + OFF_QL + row + d * 2)        = __float2bfloat16(v1 - __bfloat162float(b1));
        *(__nv_bfloat16*)(sm + OFF_QL + row + (d + 32) * 2) = __float2bfloat16(v2 - __bfloat162float(b2));
    }
    // ---- load K (+RoPE) ----
    const float* kbase = g_qkv + (size_t)(bi * NTOK) * QKVN + DIM + h * DH;
#pragma unroll 4
    for (int it = 0; it < 32; it++) {
        int jj  = grp + 8 * it;
        int tok = (widx - 1) * WS + jj;
        float x1 = 0.f, x2 = 0.f;
        if (tok >= 0) {
            const float* p = kbase + (size_t)tok * QKVN;
            x1 = p[d]; x2 = p[d + 32];
        }
        float2 sc = g_rope[jj * 32 + d];
        float v1 = x1 * sc.y - x2 * sc.x;
        float v2 = x2 * sc.y + x1 * sc.x;
        uint32_t row = jj * QK_ROWB;
        __nv_bfloat16 b1 = __float2bfloat16(v1), b2 = __float2bfloat16(v2);
        *(__nv_bfloat16*)(sm + OFF_KH + row + d * 2)        = b1;
        *(__nv_bfloat16*)(sm + OFF_KH + row + (d + 32) * 2) = b2;
        *(__nv_bfloat16*)(sm + OFF_KL + row + d * 2)        = __float2bfloat16(v1 - __bfloat162float(b1));
        *(__nv_bfloat16*)(sm + OFF_KL + row + (d + 32) * 2) = __float2bfloat16(v2 - __bfloat162float(b2));
    }
    // ---- load V transposed hi/lo ----
    const float* vbase = g_qkv + (size_t)(bi * NTOK) * QKVN + 2 * DIM + h * DH;
    for (int idx = tid; idx < 256 * 64; idx += 256) {
        int jj = idx >> 6, dd = idx & 63;
        int tok = (widx - 1) * WS + jj;
        float v = (tok < 0) ? 0.f : vbase[(size_t)tok * QKVN + dd];
        __nv_bfloat16 hv = __float2bfloat16(v);
        uint32_t off = dd * PV_ROWB + jj * 2;
        *(__nv_bfloat16*)(sm + OFF_VH + off) = hv;
        *(__nv_bfloat16*)(sm + OFF_VL + off) = __float2bfloat16(v - __bfloat162float(hv));
    }
    __syncthreads();

    // ---- S = Q K^T (bf16x3), only K-tiles [wid, wid+8] (valid column band) ----
    // acc[nt][..]: local nt 0..17 -> global 8-col tile (2*wid + nt),
    // column c = 16*wid + 8*nt + 2*q4 + e
    float acc[18][4];
#pragma unroll
    for (int nt = 0; nt < 18; nt++)
#pragma unroll
        for (int i = 0; i < 4; i++) acc[nt][i] = 0.f;

    const uint32_t lrq = (lane & 15) * QK_ROWB + (lane >> 4) * 16;
    const uint32_t lrp = (lane & 15) * PV_ROWB + (lane >> 4) * 16;

#pragma unroll
    for (int ks = 0; ks < 4; ks++) {
        const uint32_t ko = ks * 32;
        uint32_t ah[4], al_[4];
        ldm_x4(ah,  sb + OFF_QH + wid * 16 * QK_ROWB + ko + lrq);
        ldm_x4(al_, sb + OFF_QL + wid * 16 * QK_ROWB + ko + lrq);
#pragma unroll
        for (int t = 0; t < 9; t++) {
            uint32_t addr = sb + OFF_KH + (wid + t) * 16 * QK_ROWB + ko + lrq;
            uint32_t rh[4], rl[4];
            ldm_x4(rh, addr);
            ldm_x4(rl, addr + (OFF_KL - OFF_KH));
            uint32_t bh0[2] = {rh[0], rh[2]}, bh1[2] = {rh[1], rh[3]};
            uint32_t bl0[2] = {rl[0], rl[2]}, bl1[2] = {rl[1], rl[3]};
            mma16816(acc[2 * t],     ah, bh0);
            mma16816(acc[2 * t],     ah, bl0);
            mma16816(acc[2 * t],     al_, bh0);
            mma16816(acc[2 * t + 1], ah, bh1);
            mma16816(acc[2 * t + 1], ah, bl1);
            mma16816(acc[2 * t + 1], al_, bh1);
        }
    }
    __syncthreads();   // all warps done reading Q/K before P overwrites

    // ---- mask + softmax over the 144-col band, P -> smem hi/lo ----
    const int q4 = lane & 3;
    const int cbase = 16 * wid;
#pragma unroll
    for (int i01 = 0; i01 < 2; i01++) {
        int r = wid * 16 + (lane >> 2) + i01 * 8;
        float mx = -1e30f;
#pragma unroll
        for (int nt = 0; nt < 18; nt++)
#pragma unroll
            for (int e = 0; e < 2; e++) {
                int c = cbase + 8 * nt + 2 * q4 + e;
                bool keep = (c >= r) && (c <= r + WS) && (widx > 0 || c >= WS);
                float& v = acc[nt][i01 * 2 + e];
                if (!keep) v = -1e30f;
                mx = fmaxf(mx, v);
            }
        mx = fmaxf(mx, __shfl_xor_sync(0xffffffffu, mx, 1));
        mx = fmaxf(mx, __shfl_xor_sync(0xffffffffu, mx, 2));
        float sum = 0.f;
#pragma unroll
        for (int nt = 0; nt < 18; nt++)
#pragma unroll
            for (int e = 0; e < 2; e++) {
                float& v = acc[nt][i01 * 2 + e];
                v = __expf(v - mx);
                sum += v;
            }
        sum += __shfl_xor_sync(0xffffffffu, sum, 1);
        sum += __shfl_xor_sync(0xffffffffu, sum, 2);
        float inv = 1.0f / sum;
#pragma unroll
        for (int nt = 0; nt < 18; nt++)
#pragma unroll
            for (int e = 0; e < 2; e++) acc[nt][i01 * 2 + e] *= inv;

        uint32_t rowoff = (uint32_t)r * PV_ROWB;
#pragma unroll
        for (int nt = 0; nt < 18; nt++) {
            uint32_t off = rowoff + (cbase + 8 * nt + 2 * q4) * 2;
            store_hl(sm + OFF_PH, sm + OFF_PL, off,
                     acc[nt][i01 * 2], acc[nt][i01 * 2 + 1]);
        }
    }
    __syncthreads();

    // ---- O = P V (bf16x3): only k-steps [wid, wid+8] (band j in [16w,16w+143]) ----
    float o[8][4];
#pragma unroll
    for (int nt = 0; nt < 8; nt++)
#pragma unroll
        for (int i = 0; i < 4; i++) o[nt][i] = 0.f;

#pragma unroll
    for (int t = 0; t < 9; t++) {
        const uint32_t ko = (wid + t) * 32;
        uint32_t ph[4], pl[4];
        uint32_t addrA = sb + OFF_PH + wid * 16 * PV_ROWB + ko + lrp;
        ldm_x4(ph, addrA);
        ldm_x4(pl, addrA + (OFF_PL - OFF_PH));
#pragma unroll
        for (int nt2 = 0; nt2 < 4; nt2++) {
            uint32_t addrB = sb + OFF_VH + nt2 * 16 * PV_ROWB + ko + lrp;
            uint32_t rh[4], rl[4];
            ldm_x4(rh, addrB);
            ldm_x4(rl, addrB + (OFF_VL - OFF_VH));
            uint32_t vh0[2] = {rh[0], rh[2]}, vh1[2] = {rh[1], rh[3]};
            uint32_t vl0[2] = {rl[0], rl[2]}, vl1[2] = {rl[1], rl[3]};
            mma16816(o[2 * nt2],     ph, vh0);
            mma16816(o[2 * nt2],     ph, vl0);
            mma16816(o[2 * nt2],     pl, vh0);
            mma16816(o[2 * nt2 + 1], ph, vh1);
            mma16816(o[2 * nt2 + 1], ph, vl1);
            mma16816(o[2 * nt2 + 1], pl, vh1);
        }
    }

    const int gr = lane >> 2;
#pragma unroll
    for (int i01 = 0; i01 < 2; i01++) {
        int row = widx * WS + wid * 16 + gr + i01 * 8;
        size_t base = (size_t)(bi * NTOK + row) * DIM + h * DH;
#pragma unroll
        for (int nt = 0; nt < 8; nt++) {
            int col = nt * 8 + 2 * q4;
            float v0 = o[nt][i01 * 2], v1 = o[nt][i01 * 2 + 1];
            __nv_bfloat162 hv = __floats2bfloat162_rn(v0, v1);
            __nv_bfloat162 lv = __floats2bfloat162_rn(v0 - __bfloat162float(hv.x),
                                                      v1 - __bfloat162float(hv.y));
            *(__nv_bfloat162*)&g_ah[base + col] = hv;
            *(__nv_bfloat162*)&g_al[base + col] = lv;
        }
    }
}

// ---------------------------------------------------------------------------
extern "C" void kernel_launch(void* const* d_in, const int* in_sizes, int n_in,
                              void* d_out, int out_size)
{
    const float* x    = (const float*)d_in[0];
    const float* Wqkv = (const float*)d_in[1];
    const float* Wout = (const float*)d_in[2];
    float* out = (float*)d_out;

    float *qkv_p;
    __nv_bfloat16 *xh, *xl, *wqh, *wql, *woh, *wol, *ah, *al;
    cudaGetSymbolAddress((void**)&qkv_p, g_qkv);
    cudaGetSymbolAddress((void**)&xh, g_xh);   cudaGetSymbolAddress((void**)&xl, g_xl);
    cudaGetSymbolAddress((void**)&wqh, g_wqh); cudaGetSymbolAddress((void**)&wql, g_wql);
    cudaGetSymbolAddress((void**)&woh, g_woh); cudaGetSymbolAddress((void**)&wol, g_wol);
    cudaGetSymbolAddress((void**)&ah, g_ah);   cudaGetSymbolAddress((void**)&al, g_al);

    cudaFuncSetAttribute(gemm_bf16x3,
                         cudaFuncAttributeMaxDynamicSharedMemorySize, GSMEM_BYTES);
    cudaFuncSetAttribute(attn_mma_kernel,
                         cudaFuncAttributeMaxDynamicSharedMemorySize, ASMEM_BYTES);

    rope_table_kernel<<<32, 256>>>();
    split_f32<<<(MTOT * DIM / 4 + 255) / 256, 256>>>(x, xh, xl, MTOT * DIM / 4);
    transpose_split<<<dim3(QKVN / 32, DIM / 32), 256>>>(Wqkv, wqh, wql, DIM, QKVN);
    transpose_split<<<dim3(DIM / 32, DIM / 32), 256>>>(Wout, woh, wol, DIM, DIM);

    gemm_bf16x3<<<dim3(QKVN / 128, MTOT / 128), 256, GSMEM_BYTES>>>(
        xh, xl, wqh, wql, qkv_p, MTOT, QKVN, DIM);

    attn_mma_kernel<<<dim3(NWIN, NHEAD, BATCH), 256, ASMEM_BYTES>>>();

    gemm_bf16x3<<<dim3(DIM / 128, MTOT / 128), 256, GSMEM_BYTES>>>(
        ah, al, woh, wol, out, MTOT, DIM, DIM);
}

// round 9
// speedup vs baseline: 2.7166x; 1.1081x over previous
#include <cuda_runtime.h>
#include <cuda_bf16.h>
#include <math.h>
#include <stdint.h>

#define BATCH 4
#define NTOK  4096
#define DIM   1024
#define NHEAD 16
#define DH    64
#define WS    128
#define NWIN  32
#define QKVN  3072
#define MTOT  (BATCH * NTOK)   // 16384

// ---------------------------------------------------------------------------
// Scratch (static device globals: allocation-free, graph-capturable)
// ---------------------------------------------------------------------------
__device__ float         g_qkv [(size_t)MTOT * QKVN];      // f32 q|k|v
__device__ __nv_bfloat16 g_xh  [(size_t)MTOT * DIM];
__device__ __nv_bfloat16 g_xl  [(size_t)MTOT * DIM];
__device__ __nv_bfloat16 g_wqh [(size_t)QKVN * DIM];
__device__ __nv_bfloat16 g_wql [(size_t)QKVN * DIM];
__device__ __nv_bfloat16 g_woh [(size_t)DIM * DIM];
__device__ __nv_bfloat16 g_wol [(size_t)DIM * DIM];
__device__ __nv_bfloat16 g_ah  [(size_t)MTOT * DIM];
__device__ __nv_bfloat16 g_al  [(size_t)MTOT * DIM];
__device__ float2        g_rope[256 * 32];                 // (sin, cos) per (pos, d)

// ---------------------------------------------------------------------------
// Base-target primitives (compute_103 rejects tcgen05; mma.sync is legal)
// ---------------------------------------------------------------------------
__device__ __forceinline__ uint32_t smem_u32(const void* p) {
    return (uint32_t)__cvta_generic_to_shared(p);
}
__device__ __forceinline__ void cp_async16(uint32_t saddr, const void* gaddr) {
    asm volatile("cp.async.cg.shared.global [%0], [%1], 16;" :: "r"(saddr), "l"(gaddr));
}
#define CP_COMMIT()  asm volatile("cp.async.commit_group;" ::: "memory")
#define CP_WAIT(N)   asm volatile("cp.async.wait_group %0;" :: "n"(N) : "memory")

__device__ __forceinline__ void ldm_x4(uint32_t* r, uint32_t addr) {
    asm volatile("ldmatrix.sync.aligned.m8n8.x4.shared.b16 {%0,%1,%2,%3}, [%4];"
                 : "=r"(r[0]), "=r"(r[1]), "=r"(r[2]), "=r"(r[3]) : "r"(addr));
}
__device__ __forceinline__ void mma16816(float* c, const uint32_t* a, const uint32_t* b) {
    asm volatile("mma.sync.aligned.m16n8k16.row.col.f32.bf16.bf16.f32 "
                 "{%0,%1,%2,%3}, {%4,%5,%6,%7}, {%8,%9}, {%0,%1,%2,%3};"
                 : "+f"(c[0]), "+f"(c[1]), "+f"(c[2]), "+f"(c[3])
                 : "r"(a[0]), "r"(a[1]), "r"(a[2]), "r"(a[3]), "r"(b[0]), "r"(b[1]));
}

// ---------------------------------------------------------------------------
// Prep kernels
// ---------------------------------------------------------------------------
__global__ __launch_bounds__(256) void rope_table_kernel()
{
    int idx = blockIdx.x * 256 + threadIdx.x;   // 8192 entries
    if (idx >= 256 * 32) return;
    int j = idx >> 5, d = idx & 31;
    float inv_freq = expf(-logf(10000.0f) * (float)d * (1.0f / 32.0f));
    float s, c;
    sincosf((float)j * inv_freq, &s, &c);
    g_rope[idx] = make_float2(s, c);
}

__global__ __launch_bounds__(256) void split_f32(const float* __restrict__ src,
                                                 __nv_bfloat16* __restrict__ hi,
                                                 __nv_bfloat16* __restrict__ lo, int n4)
{
    int i = blockIdx.x * 256 + threadIdx.x;
    if (i >= n4) return;
    float4 v = ((const float4*)src)[i];
    float a[4] = {v.x, v.y, v.z, v.w};
#pragma unroll
    for (int j = 0; j < 4; j++) {
        __nv_bfloat16 h = __float2bfloat16(a[j]);
        hi[i * 4 + j] = h;
        lo[i * 4 + j] = __float2bfloat16(a[j] - __bfloat162float(h));
    }
}

__global__ __launch_bounds__(256) void transpose_split(const float* __restrict__ W,
                                                       __nv_bfloat16* __restrict__ Th,
                                                       __nv_bfloat16* __restrict__ Tl,
                                                       int K, int N)
{
    __shared__ float t[32][33];
    int n0 = blockIdx.x * 32, k0 = blockIdx.y * 32;
    int tx = threadIdx.x & 31, ty8 = threadIdx.x >> 5;
#pragma unroll
    for (int r = 0; r < 4; r++) {
        int ky = ty8 + r * 8;
        t[ky][tx] = W[(size_t)(k0 + ky) * N + n0 + tx];
    }
    __syncthreads();
#pragma unroll
    for (int r = 0; r < 4; r++) {
        int ny = ty8 + r * 8;
        float v = t[tx][ny];
        __nv_bfloat16 h = __float2bfloat16(v);
        Th[(size_t)(n0 + ny) * K + k0 + tx] = h;
        Tl[(size_t)(n0 + ny) * K + k0 + tx] = __float2bfloat16(v - __bfloat162float(h));
    }
}

// ---------------------------------------------------------------------------
// bf16x3 GEMM via mma.sync: 128x128 CTA tile, 256 threads (8 warps, 64x32),
// KC=32, XOR-swizzled 64B rows (conflict-free, no padding), 3-stage cp.async,
// ONE __syncthreads per chunk, 2 CTAs/SM.
// Swizzle: phys(row, c16) = (row>>1)*128 + (row&1)*64 + ((c16 ^ (row>>1))&3)*16
// (ldmatrix phase = 8 consecutive rows at fixed c16 -> all 8 16B units hit once)
// ---------------------------------------------------------------------------
#define KC       32
#define ARR_B    8192                  // 128 rows x 64B, swizzled
#define STAGE_B  (4 * ARR_B)           // 32768
#define GSMEM_BYTES (3 * STAGE_B)      // 98304 (x2 CTAs = 196608 <= 228KB)

__device__ __forceinline__ uint32_t sw_off(int row, int c16) {
    return (uint32_t)(((row >> 1) << 7) + ((row & 1) << 6)
                      + (((c16 ^ (row >> 1)) & 3) << 4));
}

__global__ __launch_bounds__(256, 2) void gemm_bf16x3(
    const __nv_bfloat16* __restrict__ Ah, const __nv_bfloat16* __restrict__ Al,
    const __nv_bfloat16* __restrict__ Bh, const __nv_bfloat16* __restrict__ Bl,
    float* __restrict__ C, int M, int N, int K)
{
    extern __shared__ char sm[];
    const uint32_t sbase = smem_u32(sm);
    const int tid  = threadIdx.x;
    const int wid  = tid >> 5;
    const int lane = tid & 31;
    const int wr   = (wid >> 2) * 64;
    const int wc   = (wid & 3) * 32;

    const int r0 = blockIdx.y * 128;
    const int c0 = blockIdx.x * 128;

    const __nv_bfloat16* gsrc[4] = {
        Ah + (size_t)r0 * K, Al + (size_t)r0 * K,
        Bh + (size_t)c0 * K, Bl + (size_t)c0 * K };

    const int ldrow = tid >> 2;          // 0..63
    const int ldseg = tid & 3;           // 0..3

    auto issue = [&](int kc, int s) {
        const uint32_t stb = sbase + s * STAGE_B;
#pragma unroll
        for (int t = 0; t < 4; t++) {
#pragma unroll
            for (int half = 0; half < 2; half++) {
                int row = ldrow + half * 64;
                const void* g = gsrc[t] + (size_t)row * K + kc * KC + ldseg * 8;
                cp_async16(stb + t * ARR_B + sw_off(row, ldseg), g);
            }
        }
    };

    float acc[4][4][4];
#pragma unroll
    for (int mt = 0; mt < 4; mt++)
#pragma unroll
        for (int nt = 0; nt < 4; nt++)
#pragma unroll
            for (int i = 0; i < 4; i++) acc[mt][nt][i] = 0.f;

    // per-lane swizzled offsets: row = base + (lane&15) with base 16-aligned
    // -> phys = base*64 + lt(c16), c16 = 2*ks + (lane>>4) in {ch, 2+ch}
    const int rl = lane & 15, chh = lane >> 4;
    const uint32_t ltb = (uint32_t)(((rl >> 1) << 7) + ((rl & 1) << 6));
    const uint32_t lt0 = ltb + ((((chh)     ^ (rl >> 1)) & 3) << 4);
    const uint32_t lt1 = ltb + ((((2 + chh) ^ (rl >> 1)) & 3) << 4);

    const int nchunk = K / KC;
    issue(0, 0); CP_COMMIT();
    issue(1, 1); CP_COMMIT();

    int buf = 0;
    for (int kc = 0; kc < nchunk; kc++) {
        if (kc + 1 < nchunk) CP_WAIT(1); else CP_WAIT(0);
        __syncthreads();
        if (kc + 2 < nchunk) {
            int nb = buf + 2; if (nb >= 3) nb -= 3;
            issue(kc + 2, nb);
            CP_COMMIT();
        }

        const uint32_t stb = sbase + buf * STAGE_B;
#pragma unroll
        for (int ks = 0; ks < 2; ks++) {
            const uint32_t lt = ks ? lt1 : lt0;
            uint32_t ah[4][4], al_[4][4];
#pragma unroll
            for (int mt = 0; mt < 4; mt++) {
                uint32_t ra = (uint32_t)(wr + mt * 16) * 64 + lt;
                ldm_x4(ah[mt],  stb + 0 * ARR_B + ra);
                ldm_x4(al_[mt], stb + 1 * ARR_B + ra);
            }
            uint32_t bh[4][2], bl[4][2];
#pragma unroll
            for (int nh = 0; nh < 2; nh++) {
                uint32_t rb = (uint32_t)(wc + nh * 16) * 64 + lt;
                uint32_t r[4];
                ldm_x4(r, stb + 2 * ARR_B + rb);
                bh[nh * 2][0] = r[0]; bh[nh * 2][1] = r[2];
                bh[nh * 2 + 1][0] = r[1]; bh[nh * 2 + 1][1] = r[3];
                ldm_x4(r, stb + 3 * ARR_B + rb);
                bl[nh * 2][0] = r[0]; bl[nh * 2][1] = r[2];
                bl[nh * 2 + 1][0] = r[1]; bl[nh * 2 + 1][1] = r[3];
            }
#pragma unroll
            for (int mt = 0; mt < 4; mt++)
#pragma unroll
                for (int nt = 0; nt < 4; nt++) {
                    mma16816(acc[mt][nt], ah[mt],  bh[nt]);
                    mma16816(acc[mt][nt], ah[mt],  bl[nt]);
                    mma16816(acc[mt][nt], al_[mt], bh[nt]);
                }
        }
        if (++buf == 3) buf = 0;
    }

    const int gr = lane >> 2;
    const int gc = (lane & 3) * 2;
#pragma unroll
    for (int mt = 0; mt < 4; mt++) {
        int row = r0 + wr + mt * 16 + gr;
#pragma unroll
        for (int nt = 0; nt < 4; nt++) {
            int col = c0 + wc + nt * 8 + gc;
            *(float2*)&C[(size_t)row * N + col] =
                make_float2(acc[mt][nt][0], acc[mt][nt][1]);
            *(float2*)&C[(size_t)(row + 8) * N + col] =
                make_float2(acc[mt][nt][2], acc[mt][nt][3]);
        }
    }
}

// ---------------------------------------------------------------------------
// Tensor-core local attention, MASK-AWARE (round-8 config, unchanged):
// warp w (rows 16w..16w+15) only touches columns [16w, 16w+143].
// ---------------------------------------------------------------------------
#define QK_ROWB 144
#define PV_ROWB 528
#define OFF_QH  0
#define OFF_QL  18432
#define OFF_KH  36864
#define OFF_KL  73728
#define OFF_PH  0
#define OFF_PL  67584
#define OFF_VH  135168
#define OFF_VL  168960
#define ASMEM_BYTES 202752

__device__ __forceinline__ void store_hl(char* base_h, char* base_l,
                                         uint32_t off, float v0, float v1) {
    __nv_bfloat162 h = __floats2bfloat162_rn(v0, v1);
    float r0 = v0 - __bfloat162float(h.x);
    float r1 = v1 - __bfloat162float(h.y);
    *(__nv_bfloat162*)(base_h + off) = h;
    *(__nv_bfloat162*)(base_l + off) = __floats2bfloat162_rn(r0, r1);
}

__global__ __launch_bounds__(256) void attn_mma_kernel()
{
    extern __shared__ char sm[];
    const uint32_t sb = smem_u32(sm);

    const int widx = blockIdx.x;
    const int h    = blockIdx.y;
    const int bi   = blockIdx.z;
    const int tid  = threadIdx.x;
    const int wid  = tid >> 5;
    const int lane = tid & 31;
    const int d    = tid & 31;
    const int grp  = tid >> 5;

    const float scale = 0.125f;

    const float* qbase = g_qkv + (size_t)(bi * NTOK + widx * WS) * QKVN + h * DH;
#pragma unroll 4
    for (int it = 0; it < 16; it++) {
        int i = grp + 8 * it;
        const float* p = qbase + (size_t)i * QKVN;
        float x1 = p[d], x2 = p[d + 32];
        float2 sc = g_rope[(WS + i) * 32 + d];
        float v1 = (x1 * sc.y - x2 * sc.x) * scale;
        float v2 = (x2 * sc.y + x1 * sc.x) * scale;
        uint32_t row = i * QK_ROWB;
        __nv_bfloat16 b1 = __float2bfloat16(v1), b2 = __float2bfloat16(v2);
        *(__nv_bfloat16*)(sm + OFF_QH + row + d * 2)        = b1;
        *(__nv_bfloat16*)(sm + OFF_QH + row + (d + 32) * 2) = b2;
        *(__nv_bfloat16*)(sm + OFF_QL + row + d * 2)        = __float2bfloat16(v1 - __bfloat162float(b1));
        *(__nv_bfloat16*)(sm + OFF_QL + row + (d + 32) * 2) = __float2bfloat16(v2 - __bfloat162float(b2));
    }
    const float* kbase = g_qkv + (size_t)(bi * NTOK) * QKVN + DIM + h * DH;
#pragma unroll 4
    for (int it = 0; it < 32; it++) {
        int jj  = grp + 8 * it;
        int tok = (widx - 1) * WS + jj;
        float x1 = 0.f, x2 = 0.f;
        if (tok >= 0) {
            const float* p = kbase + (size_t)tok * QKVN;
            x1 = p[d]; x2 = p[d + 32];
        }
        float2 sc = g_rope[jj * 32 + d];
        float v1 = x1 * sc.y - x2 * sc.x;
        float v2 = x2 * sc.y + x1 * sc.x;
        uint32_t row = jj * QK_ROWB;
        __nv_bfloat16 b1 = __float2bfloat16(v1), b2 = __float2bfloat16(v2);
        *(__nv_bfloat16*)(sm + OFF_KH + row + d * 2)        = b1;
        *(__nv_bfloat16*)(sm + OFF_KH + row + (d + 32) * 2) = b2;
        *(__nv_bfloat16*)(sm + OFF_KL + row + d * 2)        = __float2bfloat16(v1 - __bfloat162float(b1));
        *(__nv_bfloat16*)(sm + OFF_KL + row + (d + 32) * 2) = __float2bfloat16(v2 - __bfloat162float(b2));
    }
    const float* vbase = g_qkv + (size_t)(bi * NTOK) * QKVN + 2 * DIM + h * DH;
    for (int idx = tid; idx < 256 * 64; idx += 256) {
        int jj = idx >> 6, dd = idx & 63;
        int tok = (widx - 1) * WS + jj;
        float v = (tok < 0) ? 0.f : vbase[(size_t)tok * QKVN + dd];
        __nv_bfloat16 hv = __float2bfloat16(v);
        uint32_t off = dd * PV_ROWB + jj * 2;
        *(__nv_bfloat16*)(sm + OFF_VH + off) = hv;
        *(__nv_bfloat16*)(sm + OFF_VL + off) = __float2bfloat16(v - __bfloat162float(hv));
    }
    __syncthreads();

    float acc[18][4];
#pragma unroll
    for (int nt = 0; nt < 18; nt++)
#pragma unroll
        for (int i = 0; i < 4; i++) acc[nt][i] = 0.f;

    const uint32_t lrq = (lane & 15) * QK_ROWB + (lane >> 4) * 16;
    const uint32_t lrp = (lane & 15) * PV_ROWB + (lane >> 4) * 16;

#pragma unroll
    for (int ks = 0; ks < 4; ks++) {
        const uint32_t ko = ks * 32;
        uint32_t ah[4], al_[4];
        ldm_x4(ah,  sb + OFF_QH + wid * 16 * QK_ROWB + ko + lrq);
        ldm_x4(al_, sb + OFF_QL + wid * 16 * QK_ROWB + ko + lrq);
#pragma unroll
        for (int t = 0; t < 9; t++) {
            uint32_t addr = sb + OFF_KH + (wid + t) * 16 * QK_ROWB + ko + lrq;
            uint32_t rh[4], rl[4];
            ldm_x4(rh, addr);
            ldm_x4(rl, addr + (OFF_KL - OFF_KH));
            uint32_t bh0[2] = {rh[0], rh[2]}, bh1[2] = {rh[1], rh[3]};
            uint32_t bl0[2] = {rl[0], rl[2]}, bl1[2] = {rl[1], rl[3]};
            mma16816(acc[2 * t],     ah, bh0);
            mma16816(acc[2 * t],     ah, bl0);
            mma16816(acc[2 * t],     al_, bh0);
            mma16816(acc[2 * t + 1], ah, bh1);
            mma16816(acc[2 * t + 1], ah, bl1);
            mma16816(acc[2 * t + 1], al_, bh1);
        }
    }
    __syncthreads();

    const int q4 = lane & 3;
    const int cbase = 16 * wid;
#pragma unroll
    for (int i01 = 0; i01 < 2; i01++) {
        int r = wid * 16 + (lane >> 2) + i01 * 8;
        float mx = -1e30f;
#pragma unroll
        for (int nt = 0; nt < 18; nt++)
#pragma unroll
            for (int e = 0; e < 2; e++) {
                int c = cbase + 8 * nt + 2 * q4 + e;
                bool keep = (c >= r) && (c <= r + WS) && (widx > 0 || c >= WS);
                float& v = acc[nt][i01 * 2 + e];
                if (!keep) v = -1e30f;
                mx = fmaxf(mx, v);
            }
        mx = fmaxf(mx, __shfl_xor_sync(0xffffffffu, mx, 1));
        mx = fmaxf(mx, __shfl_xor_sync(0xffffffffu, mx, 2));
        float sum = 0.f;
#pragma unroll
        for (int nt = 0; nt < 18; nt++)
#pragma unroll
            for (int e = 0; e < 2; e++) {
                float& v = acc[nt][i01 * 2 + e];
                v = __expf(v - mx);
                sum += v;
            }
        sum += __shfl_xor_sync(0xffffffffu, sum, 1);
        sum += __shfl_xor_sync(0xffffffffu, sum, 2);
        float inv = 1.0f / sum;
#pragma unroll
        for (int nt = 0; nt < 18; nt++)
#pragma unroll
            for (int e = 0; e < 2; e++) acc[nt][i01 * 2 + e] *= inv;

        uint32_t rowoff = (uint32_t)r * PV_ROWB;
#pragma unroll
        for (int nt = 0; nt < 18; nt++) {
            uint32_t off = rowoff + (cbase + 8 * nt + 2 * q4) * 2;
            store_hl(sm + OFF_PH, sm + OFF_PL, off,
                     acc[nt][i01 * 2], acc[nt][i01 * 2 + 1]);
        }
    }
    __syncthreads();

    float o[8][4];
#pragma unroll
    for (int nt = 0; nt < 8; nt++)
#pragma unroll
        for (int i = 0; i < 4; i++) o[nt][i] = 0.f;

#pragma unroll
    for (int t = 0; t < 9; t++) {
        const uint32_t ko = (wid + t) * 32;
        uint32_t ph[4], pl[4];
        uint32_t addrA = sb + OFF_PH + wid * 16 * PV_ROWB + ko + lrp;
        ldm_x4(ph, addrA);
        ldm_x4(pl, addrA + (OFF_PL - OFF_PH));
#pragma unroll
        for (int nt2 = 0; nt2 < 4; nt2++) {
            uint32_t addrB = sb + OFF_VH + nt2 * 16 * PV_ROWB + ko + lrp;
            uint32_t rh[4], rl[4];
            ldm_x4(rh, addrB);
            ldm_x4(rl, addrB + (OFF_VL - OFF_VH));
            uint32_t vh0[2] = {rh[0], rh[2]}, vh1[2] = {rh[1], rh[3]};
            uint32_t vl0[2] = {rl[0], rl[2]}, vl1[2] = {rl[1], rl[3]};
            mma16816(o[2 * nt2],     ph, vh0);
            mma16816(o[2 * nt2],     ph, vl0);
            mma16816(o[2 * nt2],     pl, vh0);
            mma16816(o[2 * nt2 + 1], ph, vh1);
            mma16816(o[2 * nt2 + 1], ph, vl1);
            mma16816(o[2 * nt2 + 1], pl, vh1);
        }
    }

    const int gr = lane >> 2;
#pragma unroll
    for (int i01 = 0; i01 < 2; i01++) {
        int row = widx * WS + wid * 16 + gr + i01 * 8;
        size_t base = (size_t)(bi * NTOK + row) * DIM + h * DH;
#pragma unroll
        for (int nt = 0; nt < 8; nt++) {
            int col = nt * 8 + 2 * q4;
            float v0 = o[nt][i01 * 2], v1 = o[nt][i01 * 2 + 1];
            __nv_bfloat162 hv = __floats2bfloat162_rn(v0, v1);
            __nv_bfloat162 lv = __floats2bfloat162_rn(v0 - __bfloat162float(hv.x),
                                                      v1 - __bfloat162float(hv.y));
            *(__nv_bfloat162*)&g_ah[base + col] = hv;
            *(__nv_bfloat162*)&g_al[base + col] = lv;
        }
    }
}

// ---------------------------------------------------------------------------
extern "C" void kernel_launch(void* const* d_in, const int* in_sizes, int n_in,
                              void* d_out, int out_size)
{
    const float* x    = (const float*)d_in[0];
    const float* Wqkv = (const float*)d_in[1];
    const float* Wout = (const float*)d_in[2];
    float* out = (float*)d_out;

    float *qkv_p;
    __nv_bfloat16 *xh, *xl, *wqh, *wql, *woh, *wol, *ah, *al;
    cudaGetSymbolAddress((void**)&qkv_p, g_qkv);
    cudaGetSymbolAddress((void**)&xh, g_xh);   cudaGetSymbolAddress((void**)&xl, g_xl);
    cudaGetSymbolAddress((void**)&wqh, g_wqh); cudaGetSymbolAddress((void**)&wql, g_wql);
    cudaGetSymbolAddress((void**)&woh, g_woh); cudaGetSymbolAddress((void**)&wol, g_wol);
    cudaGetSymbolAddress((void**)&ah, g_ah);   cudaGetSymbolAddress((void**)&al, g_al);

    cudaFuncSetAttribute(gemm_bf16x3,
                         cudaFuncAttributeMaxDynamicSharedMemorySize, GSMEM_BYTES);
    cudaFuncSetAttribute(attn_mma_kernel,
                         cudaFuncAttributeMaxDynamicSharedMemorySize, ASMEM_BYTES);

    rope_table_kernel<<<32, 256>>>();
    split_f32<<<(MTOT * DIM / 4 + 255) / 256, 256>>>(x, xh, xl, MTOT * DIM / 4);
    transpose_split<<<dim3(QKVN / 32, DIM / 32), 256>>>(Wqkv, wqh, wql, DIM, QKVN);
    transpose_split<<<dim3(DIM / 32, DIM / 32), 256>>>(Wout, woh, wol, DIM, DIM);

    gemm_bf16x3<<<dim3(QKVN / 128, MTOT / 128), 256, GSMEM_BYTES>>>(
        xh, xl, wqh, wql, qkv_p, MTOT, QKVN, DIM);

    attn_mma_kernel<<<dim3(NWIN, NHEAD, BATCH), 256, ASMEM_BYTES>>>();

    gemm_bf16x3<<<dim3(DIM / 128, MTOT / 128), 256, GSMEM_BYTES>>>(
        ah, al, woh, wol, out, MTOT, DIM, DIM);
}

// round 11
// speedup vs baseline: 2.7438x; 1.0100x over previous
#include <cuda_runtime.h>
#include <cuda_bf16.h>
#include <math.h>
#include <stdint.h>

#define BATCH 4
#define NTOK  4096
#define DIM   1024
#define NHEAD 16
#define DH    64
#define WS    128
#define NWIN  32
#define QKVN  3072
#define MTOT  (BATCH * NTOK)   // 16384

// ---------------------------------------------------------------------------
// Scratch (static device globals: allocation-free, graph-capturable)
// ---------------------------------------------------------------------------
__device__ float         g_qkv [(size_t)MTOT * QKVN];      // f32 q|k|v
__device__ __nv_bfloat16 g_xh  [(size_t)MTOT * DIM];
__device__ __nv_bfloat16 g_xl  [(size_t)MTOT * DIM];
__device__ __nv_bfloat16 g_wqh [(size_t)QKVN * DIM];
__device__ __nv_bfloat16 g_wql [(size_t)QKVN * DIM];
__device__ __nv_bfloat16 g_woh [(size_t)DIM * DIM];
__device__ __nv_bfloat16 g_wol [(size_t)DIM * DIM];
__device__ __nv_bfloat16 g_ah  [(size_t)MTOT * DIM];
__device__ __nv_bfloat16 g_al  [(size_t)MTOT * DIM];
__device__ float2        g_rope[256 * 32];                 // (sin, cos) per (pos, d)

// ---------------------------------------------------------------------------
// Base-target primitives (compute_103 rejects tcgen05; mma.sync is legal)
// ---------------------------------------------------------------------------
__device__ __forceinline__ uint32_t smem_u32(const void* p) {
    return (uint32_t)__cvta_generic_to_shared(p);
}
__device__ __forceinline__ void cp_async16(uint32_t saddr, const void* gaddr) {
    asm volatile("cp.async.cg.shared.global [%0], [%1], 16;" :: "r"(saddr), "l"(gaddr));
}
#define CP_COMMIT()  asm volatile("cp.async.commit_group;" ::: "memory")
#define CP_WAIT(N)   asm volatile("cp.async.wait_group %0;" :: "n"(N) : "memory")

__device__ __forceinline__ void ldm_x4(uint32_t* r, uint32_t addr) {
    asm volatile("ldmatrix.sync.aligned.m8n8.x4.shared.b16 {%0,%1,%2,%3}, [%4];"
                 : "=r"(r[0]), "=r"(r[1]), "=r"(r[2]), "=r"(r[3]) : "r"(addr));
}
__device__ __forceinline__ void mma16816(float* c, const uint32_t* a, const uint32_t* b) {
    asm volatile("mma.sync.aligned.m16n8k16.row.col.f32.bf16.bf16.f32 "
                 "{%0,%1,%2,%3}, {%4,%5,%6,%7}, {%8,%9}, {%0,%1,%2,%3};"
                 : "+f"(c[0]), "+f"(c[1]), "+f"(c[2]), "+f"(c[3])
                 : "r"(a[0]), "r"(a[1]), "r"(a[2]), "r"(a[3]), "r"(b[0]), "r"(b[1]));
}
__device__ __forceinline__ uint32_t pack_bf16x2(float a, float b) {
    __nv_bfloat162 h = __floats2bfloat162_rn(a, b);
    uint32_t u; *(__nv_bfloat162*)&u = h;
    return u;
}

// ---------------------------------------------------------------------------
// Prep kernels
// ---------------------------------------------------------------------------
__global__ __launch_bounds__(256) void rope_table_kernel()
{
    int idx = blockIdx.x * 256 + threadIdx.x;   // 8192 entries
    if (idx >= 256 * 32) return;
    int j = idx >> 5, d = idx & 31;
    float inv_freq = expf(-logf(10000.0f) * (float)d * (1.0f / 32.0f));
    float s, c;
    sincosf((float)j * inv_freq, &s, &c);
    g_rope[idx] = make_float2(s, c);
}

__global__ __launch_bounds__(256) void split_f32(const float* __restrict__ src,
                                                 __nv_bfloat16* __restrict__ hi,
                                                 __nv_bfloat16* __restrict__ lo, int n4)
{
    int i = blockIdx.x * 256 + threadIdx.x;
    if (i >= n4) return;
    float4 v = ((const float4*)src)[i];
    float a[4] = {v.x, v.y, v.z, v.w};
#pragma unroll
    for (int j = 0; j < 4; j++) {
        __nv_bfloat16 h = __float2bfloat16(a[j]);
        hi[i * 4 + j] = h;
        lo[i * 4 + j] = __float2bfloat16(a[j] - __bfloat162float(h));
    }
}

__global__ __launch_bounds__(256) void transpose_split(const float* __restrict__ W,
                                                       __nv_bfloat16* __restrict__ Th,
                                                       __nv_bfloat16* __restrict__ Tl,
                                                       int K, int N)
{
    __shared__ float t[32][33];
    int n0 = blockIdx.x * 32, k0 = blockIdx.y * 32;
    int tx = threadIdx.x & 31, ty8 = threadIdx.x >> 5;
#pragma unroll
    for (int r = 0; r < 4; r++) {
        int ky = ty8 + r * 8;
        t[ky][tx] = W[(size_t)(k0 + ky) * N + n0 + tx];
    }
    __syncthreads();
#pragma unroll
    for (int r = 0; r < 4; r++) {
        int ny = ty8 + r * 8;
        float v = t[tx][ny];
        __nv_bfloat16 h = __float2bfloat16(v);
        Th[(size_t)(n0 + ny) * K + k0 + tx] = h;
        Tl[(size_t)(n0 + ny) * K + k0 + tx] = __float2bfloat16(v - __bfloat162float(h));
    }
}

// ---------------------------------------------------------------------------
// bf16x3 GEMM via mma.sync: 128x128 CTA tile, 256 threads (8 warps, 64x32),
// KC=32, XOR-swizzled 64B rows, 3-stage cp.async, ONE barrier/chunk, 2 CTAs/SM.
// (round-9 config, unchanged — control)
// ---------------------------------------------------------------------------
#define KC       32
#define ARR_B    8192
#define STAGE_B  (4 * ARR_B)           // 32768
#define GSMEM_BYTES (3 * STAGE_B)      // 98304

__device__ __forceinline__ uint32_t sw_off(int row, int c16) {
    return (uint32_t)(((row >> 1) << 7) + ((row & 1) << 6)
                      + (((c16 ^ (row >> 1)) & 3) << 4));
}

__global__ __launch_bounds__(256, 2) void gemm_bf16x3(
    const __nv_bfloat16* __restrict__ Ah, const __nv_bfloat16* __restrict__ Al,
    const __nv_bfloat16* __restrict__ Bh, const __nv_bfloat16* __restrict__ Bl,
    float* __restrict__ C, int M, int N, int K)
{
    extern __shared__ char sm[];
    const uint32_t sbase = smem_u32(sm);
    const int tid  = threadIdx.x;
    const int wid  = tid >> 5;
    const int lane = tid & 31;
    const int wr   = (wid >> 2) * 64;
    const int wc   = (wid & 3) * 32;

    const int r0 = blockIdx.y * 128;
    const int c0 = blockIdx.x * 128;

    const __nv_bfloat16* gsrc[4] = {
        Ah + (size_t)r0 * K, Al + (size_t)r0 * K,
        Bh + (size_t)c0 * K, Bl + (size_t)c0 * K };

    const int ldrow = tid >> 2;
    const int ldseg = tid & 3;

    auto issue = [&](int kc, int s) {
        const uint32_t stb = sbase + s * STAGE_B;
#pragma unroll
        for (int t = 0; t < 4; t++) {
#pragma unroll
            for (int half = 0; half < 2; half++) {
                int row = ldrow + half * 64;
                const void* g = gsrc[t] + (size_t)row * K + kc * KC + ldseg * 8;
                cp_async16(stb + t * ARR_B + sw_off(row, ldseg), g);
            }
        }
    };

    float acc[4][4][4];
#pragma unroll
    for (int mt = 0; mt < 4; mt++)
#pragma unroll
        for (int nt = 0; nt < 4; nt++)
#pragma unroll
            for (int i = 0; i < 4; i++) acc[mt][nt][i] = 0.f;

    const int rl = lane & 15, chh = lane >> 4;
    const uint32_t ltb = (uint32_t)(((rl >> 1) << 7) + ((rl & 1) << 6));
    const uint32_t lt0 = ltb + ((((chh)     ^ (rl >> 1)) & 3) << 4);
    const uint32_t lt1 = ltb + ((((2 + chh) ^ (rl >> 1)) & 3) << 4);

    const int nchunk = K / KC;
    issue(0, 0); CP_COMMIT();
    issue(1, 1); CP_COMMIT();

    int buf = 0;
    for (int kc = 0; kc < nchunk; kc++) {
        if (kc + 1 < nchunk) CP_WAIT(1); else CP_WAIT(0);
        __syncthreads();
        if (kc + 2 < nchunk) {
            int nb = buf + 2; if (nb >= 3) nb -= 3;
            issue(kc + 2, nb);
            CP_COMMIT();
        }

        const uint32_t stb = sbase + buf * STAGE_B;
#pragma unroll
        for (int ks = 0; ks < 2; ks++) {
            const uint32_t lt = ks ? lt1 : lt0;
            uint32_t ah[4][4], al_[4][4];
#pragma unroll
            for (int mt = 0; mt < 4; mt++) {
                uint32_t ra = (uint32_t)(wr + mt * 16) * 64 + lt;
                ldm_x4(ah[mt],  stb + 0 * ARR_B + ra);
                ldm_x4(al_[mt], stb + 1 * ARR_B + ra);
            }
            uint32_t bh[4][2], bl[4][2];
#pragma unroll
            for (int nh = 0; nh < 2; nh++) {
                uint32_t rb = (uint32_t)(wc + nh * 16) * 64 + lt;
                uint32_t r[4];
                ldm_x4(r, stb + 2 * ARR_B + rb);
                bh[nh * 2][0] = r[0]; bh[nh * 2][1] = r[2];
                bh[nh * 2 + 1][0] = r[1]; bh[nh * 2 + 1][1] = r[3];
                ldm_x4(r, stb + 3 * ARR_B + rb);
                bl[nh * 2][0] = r[0]; bl[nh * 2][1] = r[2];
                bl[nh * 2 + 1][0] = r[1]; bl[nh * 2 + 1][1] = r[3];
            }
#pragma unroll
            for (int mt = 0; mt < 4; mt++)
#pragma unroll
                for (int nt = 0; nt < 4; nt++) {
                    mma16816(acc[mt][nt], ah[mt],  bh[nt]);
                    mma16816(acc[mt][nt], ah[mt],  bl[nt]);
                    mma16816(acc[mt][nt], al_[mt], bh[nt]);
                }
        }
        if (++buf == 3) buf = 0;
    }

    const int gr = lane >> 2;
    const int gc = (lane & 3) * 2;
#pragma unroll
    for (int mt = 0; mt < 4; mt++) {
        int row = r0 + wr + mt * 16 + gr;
#pragma unroll
        for (int nt = 0; nt < 4; nt++) {
            int col = c0 + wc + nt * 8 + gc;
            *(float2*)&C[(size_t)row * N + col] =
                make_float2(acc[mt][nt][0], acc[mt][nt][1]);
            *(float2*)&C[(size_t)(row + 8) * N + col] =
                make_float2(acc[mt][nt][2], acc[mt][nt][3]);
        }
    }
}

// ---------------------------------------------------------------------------
// Tensor-core local attention, mask-aware, P ENTIRELY IN REGISTERS:
// the S C-fragment layout == PV A-fragment layout, so softmax output feeds
// the PV MMA directly. One __syncthreads total. Softmax normalization
// deferred to the f32 epilogue.
// ---------------------------------------------------------------------------
#define QK_ROWB 144
#define PV_ROWB 528
#define OFF_QH  0
#define OFF_QL  18432                  // 128*144
#define OFF_KH  36864
#define OFF_KL  73728                  // +256*144
#define OFF_VH  110592                 // +256*144
#define OFF_VL  144384                 // +64*528
#define ASMEM_BYTES 178176             // +64*528

__global__ __launch_bounds__(256) void attn_mma_kernel()
{
    extern __shared__ char sm[];
    const uint32_t sb = smem_u32(sm);

    const int widx = blockIdx.x;
    const int h    = blockIdx.y;
    const int bi   = blockIdx.z;
    const int tid  = threadIdx.x;
    const int wid  = tid >> 5;
    const int lane = tid & 31;
    const int d    = tid & 31;
    const int grp  = tid >> 5;

    const float scale = 0.125f;

    // ---- load Q (+scale +RoPE from table) -> bf16 hi/lo ----
    const float* qbase = g_qkv + (size_t)(bi * NTOK + widx * WS) * QKVN + h * DH;
#pragma unroll 4
    for (int it = 0; it < 16; it++) {
        int i = grp + 8 * it;
        const float* p = qbase + (size_t)i * QKVN;
        float x1 = p[d], x2 = p[d + 32];
        float2 sc = g_rope[(WS + i) * 32 + d];
        float v1 = (x1 * sc.y - x2 * sc.x) * scale;
        float v2 = (x2 * sc.y + x1 * sc.x) * scale;
        uint32_t row = i * QK_ROWB;
        __nv_bfloat16 b1 = __float2bfloat16(v1), b2 = __float2bfloat16(v2);
        *(__nv_bfloat16*)(sm + OFF_QH + row + d * 2)        = b1;
        *(__nv_bfloat16*)(sm + OFF_QH + row + (d + 32) * 2) = b2;
        *(__nv_bfloat16*)(sm + OFF_QL + row + d * 2)        = __float2bfloat16(v1 - __bfloat162float(b1));
        *(__nv_bfloat16*)(sm + OFF_QL + row + (d + 32) * 2) = __float2bfloat16(v2 - __bfloat162float(b2));
    }
    // ---- load K (+RoPE) ----
    const float* kbase = g_qkv + (size_t)(bi * NTOK) * QKVN + DIM + h * DH;
#pragma unroll 4
    for (int it = 0; it < 32; it++) {
        int jj  = grp + 8 * it;
        int tok = (widx - 1) * WS + jj;
        float x1 = 0.f, x2 = 0.f;
        if (tok >= 0) {
            const float* p = kbase + (size_t)tok * QKVN;
            x1 = p[d]; x2 = p[d + 32];
        }
        float2 sc = g_rope[jj * 32 + d];
        float v1 = x1 * sc.y - x2 * sc.x;
        float v2 = x2 * sc.y + x1 * sc.x;
        uint32_t row = jj * QK_ROWB;
        __nv_bfloat16 b1 = __float2bfloat16(v1), b2 = __float2bfloat16(v2);
        *(__nv_bfloat16*)(sm + OFF_KH + row + d * 2)        = b1;
        *(__nv_bfloat16*)(sm + OFF_KH + row + (d + 32) * 2) = b2;
        *(__nv_bfloat16*)(sm + OFF_KL + row + d * 2)        = __float2bfloat16(v1 - __bfloat162float(b1));
        *(__nv_bfloat16*)(sm + OFF_KL + row + (d + 32) * 2) = __float2bfloat16(v2 - __bfloat162float(b2));
    }
    // ---- load V transposed hi/lo ----
    const float* vbase = g_qkv + (size_t)(bi * NTOK) * QKVN + 2 * DIM + h * DH;
    for (int idx = tid; idx < 256 * 64; idx += 256) {
        int jj = idx >> 6, dd = idx & 63;
        int tok = (widx - 1) * WS + jj;
        float v = (tok < 0) ? 0.f : vbase[(size_t)tok * QKVN + dd];
        __nv_bfloat16 hv = __float2bfloat16(v);
        uint32_t off = dd * PV_ROWB + jj * 2;
        *(__nv_bfloat16*)(sm + OFF_VH + off) = hv;
        *(__nv_bfloat16*)(sm + OFF_VL + off) = __float2bfloat16(v - __bfloat162float(hv));
    }
    __syncthreads();   // the ONLY barrier

    // ---- S = Q K^T (bf16x3), K-tiles [wid, wid+8] (valid column band) ----
    float acc[18][4];
#pragma unroll
    for (int nt = 0; nt < 18; nt++)
#pragma unroll
        for (int i = 0; i < 4; i++) acc[nt][i] = 0.f;

    const uint32_t lrq = (lane & 15) * QK_ROWB + (lane >> 4) * 16;
    const uint32_t lrp = (lane & 15) * PV_ROWB + (lane >> 4) * 16;

#pragma unroll
    for (int ks = 0; ks < 4; ks++) {
        const uint32_t ko = ks * 32;
        uint32_t ah[4], al_[4];
        ldm_x4(ah,  sb + OFF_QH + wid * 16 * QK_ROWB + ko + lrq);
        ldm_x4(al_, sb + OFF_QL + wid * 16 * QK_ROWB + ko + lrq);
#pragma unroll
        for (int t = 0; t < 9; t++) {
            uint32_t addr = sb + OFF_KH + (wid + t) * 16 * QK_ROWB + ko + lrq;
            uint32_t rh[4], rl[4];
            ldm_x4(rh, addr);
            ldm_x4(rl, addr + (OFF_KL - OFF_KH));
            uint32_t bh0[2] = {rh[0], rh[2]}, bh1[2] = {rh[1], rh[3]};
            uint32_t bl0[2] = {rl[0], rl[2]}, bl1[2] = {rl[1], rl[3]};
            mma16816(acc[2 * t],     ah, bh0);
            mma16816(acc[2 * t],     ah, bl0);
            mma16816(acc[2 * t],     al_, bh0);
            mma16816(acc[2 * t + 1], ah, bh1);
            mma16816(acc[2 * t + 1], ah, bl1);
            mma16816(acc[2 * t + 1], al_, bh1);
        }
    }

    // ---- mask + softmax in registers (exp only; normalization deferred) ----
    const int q4 = lane & 3;
    const int cbase = 16 * wid;
    float inv[2];
#pragma unroll
    for (int i01 = 0; i01 < 2; i01++) {
        int r = wid * 16 + (lane >> 2) + i01 * 8;
        float mx = -1e30f;
#pragma unroll
        for (int nt = 0; nt < 18; nt++)
#pragma unroll
            for (int e = 0; e < 2; e++) {
                int c = cbase + 8 * nt + 2 * q4 + e;
                bool keep = (c >= r) && (c <= r + WS) && (widx > 0 || c >= WS);
                float& v = acc[nt][i01 * 2 + e];
                if (!keep) v = -1e30f;
                mx = fmaxf(mx, v);
            }
        mx = fmaxf(mx, __shfl_xor_sync(0xffffffffu, mx, 1));
        mx = fmaxf(mx, __shfl_xor_sync(0xffffffffu, mx, 2));
        float sum = 0.f;
#pragma unroll
        for (int nt = 0; nt < 18; nt++)
#pragma unroll
            for (int e = 0; e < 2; e++) {
                float& v = acc[nt][i01 * 2 + e];
                v = __expf(v - mx);
                sum += v;
            }
        sum += __shfl_xor_sync(0xffffffffu, sum, 1);
        sum += __shfl_xor_sync(0xffffffffu, sum, 2);
        inv[i01] = 1.0f / sum;
    }

    // ---- O = P V (bf16x3), P fragments built directly from acc registers ----
    float o[8][4];
#pragma unroll
    for (int nt = 0; nt < 8; nt++)
#pragma unroll
        for (int i = 0; i < 4; i++) o[nt][i] = 0.f;

#pragma unroll
    for (int t = 0; t < 9; t++) {
        // A-fragment (rows = this warp's 16, k-cols 16(wid+t)..+15):
        // a[0]=tile2t/rows0-7, a[1]=tile2t/rows8-15, a[2..3]=tile2t+1
        uint32_t ph[4], pl[4];
#pragma unroll
        for (int rr = 0; rr < 2; rr++) {
            const float* f = acc[2 * t + rr];
            uint32_t h0 = pack_bf16x2(f[0], f[1]);
            uint32_t h1 = pack_bf16x2(f[2], f[3]);
            __nv_bfloat162 hb0 = *(__nv_bfloat162*)&h0;
            __nv_bfloat162 hb1 = *(__nv_bfloat162*)&h1;
            ph[2 * rr]     = h0;
            ph[2 * rr + 1] = h1;
            pl[2 * rr]     = pack_bf16x2(f[0] - __bfloat162float(hb0.x),
                                         f[1] - __bfloat162float(hb0.y));
            pl[2 * rr + 1] = pack_bf16x2(f[2] - __bfloat162float(hb1.x),
                                         f[3] - __bfloat162float(hb1.y));
        }
        const uint32_t ko = (wid + t) * 32;
#pragma unroll
        for (int nt2 = 0; nt2 < 4; nt2++) {
            uint32_t addrB = sb + OFF_VH + nt2 * 16 * PV_ROWB + ko + lrp;
            uint32_t rh[4], rl[4];
            ldm_x4(rh, addrB);
            ldm_x4(rl, addrB + (OFF_VL - OFF_VH));
            uint32_t vh0[2] = {rh[0], rh[2]}, vh1[2] = {rh[1], rh[3]};
            uint32_t vl0[2] = {rl[0], rl[2]}, vl1[2] = {rl[1], rl[3]};
            mma16816(o[2 * nt2],     ph, vh0);
            mma16816(o[2 * nt2],     ph, vl0);
            mma16816(o[2 * nt2],     pl, vh0);
            mma16816(o[2 * nt2 + 1], ph, vh1);
            mma16816(o[2 * nt2 + 1], ph, vl1);
            mma16816(o[2 * nt2 + 1], pl, vh1);
        }
    }

    // ---- epilogue: normalize rows, write bf16 hi/lo ----
    const int gr = lane >> 2;
#pragma unroll
    for (int i01 = 0; i01 < 2; i01++) {
        int row = widx * WS + wid * 16 + gr + i01 * 8;
        size_t base = (size_t)(bi * NTOK + row) * DIM + h * DH;
        float nrm = inv[i01];
#pragma unroll
        for (int nt = 0; nt < 8; nt++) {
            int col = nt * 8 + 2 * q4;
            float v0 = o[nt][i01 * 2] * nrm, v1 = o[nt][i01 * 2 + 1] * nrm;
            __nv_bfloat162 hv = __floats2bfloat162_rn(v0, v1);
            __nv_bfloat162 lv = __floats2bfloat162_rn(v0 - __bfloat162float(hv.x),
                                                      v1 - __bfloat162float(hv.y));
            *(__nv_bfloat162*)&g_ah[base + col] = hv;
            *(__nv_bfloat162*)&g_al[base + col] = lv;
        }
    }
}

// ---------------------------------------------------------------------------
extern "C" void kernel_launch(void* const* d_in, const int* in_sizes, int n_in,
                              void* d_out, int out_size)
{
    const float* x    = (const float*)d_in[0];
    const float* Wqkv = (const float*)d_in[1];
    const float* Wout = (const float*)d_in[2];
    float* out = (float*)d_out;

    float *qkv_p;
    __nv_bfloat16 *xh, *xl, *wqh, *wql, *woh, *wol, *ah, *al;
    cudaGetSymbolAddress((void**)&qkv_p, g_qkv);
    cudaGetSymbolAddress((void**)&xh, g_xh);   cudaGetSymbolAddress((void**)&xl, g_xl);
    cudaGetSymbolAddress((void**)&wqh, g_wqh); cudaGetSymbolAddress((void**)&wql, g_wql);
    cudaGetSymbolAddress((void**)&woh, g_woh); cudaGetSymbolAddress((void**)&wol, g_wol);
    cudaGetSymbolAddress((void**)&ah, g_ah);   cudaGetSymbolAddress((void**)&al, g_al);

    cudaFuncSetAttribute(gemm_bf16x3,
                         cudaFuncAttributeMaxDynamicSharedMemorySize, GSMEM_BYTES);
    cudaFuncSetAttribute(attn_mma_kernel,
                         cudaFuncAttributeMaxDynamicSharedMemorySize, ASMEM_BYTES);

    rope_table_kernel<<<32, 256>>>();
    split_f32<<<(MTOT * DIM / 4 + 255) / 256, 256>>>(x, xh, xl, MTOT * DIM / 4);
    transpose_split<<<dim3(QKVN / 32, DIM / 32), 256>>>(Wqkv, wqh, wql, DIM, QKVN);
    transpose_split<<<dim3(DIM / 32, DIM / 32), 256>>>(Wout, woh, wol, DIM, DIM);

    gemm_bf16x3<<<dim3(QKVN / 128, MTOT / 128), 256, GSMEM_BYTES>>>(
        xh, xl, wqh, wql, qkv_p, MTOT, QKVN, DIM);

    attn_mma_kernel<<<dim3(NWIN, NHEAD, BATCH), 256, ASMEM_BYTES>>>();

    gemm_bf16x3<<<dim3(DIM / 128, MTOT / 128), 256, GSMEM_BYTES>>>(
        ah, al, woh, wol, out, MTOT, DIM, DIM);
}